// round 6
// baseline (speedup 1.0000x reference)
#include <cuda_runtime.h>
#include <cstdint>
#include <math.h>

// ---------------------------------------------------------------------------
// Problem sizes
// ---------------------------------------------------------------------------
constexpr int BBATCH = 8;
constexpr int SEQ    = 2048;
constexpr int DIM    = 1024;

// ---------------------------------------------------------------------------
// Scratch (static device globals — allocation-guard safe)
// ---------------------------------------------------------------------------
__device__ float g_xr    [(size_t)BBATCH * SEQ * DIM];      //  64 MB rounded x
__device__ float g_qkv   [(size_t)BBATCH * SEQ * 3 * DIM];  // 192 MB
__device__ float g_scores[(size_t)BBATCH * SEQ * SEQ];      // 128 MB
__device__ float g_att   [(size_t)BBATCH * SEQ * DIM];      //  64 MB
__device__ float g_vT    [(size_t)BBATCH * DIM * SEQ];      //  64 MB V^T per batch
__device__ float g_wqkvT [(size_t)3 * DIM * DIM];           //  12 MB
__device__ float g_woutT [(size_t)DIM * DIM];               //   4 MB

// ---------------------------------------------------------------------------
// Helpers (all baseline PTX — nothing sm_103a-gated)
// ---------------------------------------------------------------------------
__device__ __forceinline__ float tf32r(float x) {           // round-to-nearest tf32
    uint32_t u;
    asm("cvt.rna.tf32.f32 %0, %1;" : "=r"(u) : "f"(x));
    return __uint_as_float(u);
}

__device__ __forceinline__ uint32_t s2u(const void* p) {
    uint32_t a;
    asm("{ .reg .u64 t; cvta.to.shared.u64 t, %1; cvt.u32.u64 %0, t; }"
        : "=r"(a) : "l"(p));
    return a;
}

__device__ __forceinline__ void cpa16(uint32_t s, const void* g) {
    asm volatile("cp.async.cg.shared.global [%0], [%1], 16;" :: "r"(s), "l"(g));
}

__device__ __forceinline__ void ldsm4(uint32_t r[4], uint32_t addr) {
    asm volatile("ldmatrix.sync.aligned.m8n8.x4.shared.b16 {%0,%1,%2,%3}, [%4];"
                 : "=r"(r[0]), "=r"(r[1]), "=r"(r[2]), "=r"(r[3]) : "r"(addr));
}

__device__ __forceinline__ void mma8(float c[4], const uint32_t a[4],
                                     uint32_t b0, uint32_t b1) {
    asm volatile(
        "mma.sync.aligned.m16n8k8.row.col.f32.tf32.tf32.f32 "
        "{%0,%1,%2,%3}, {%4,%5,%6,%7}, {%8,%9}, {%0,%1,%2,%3};"
        : "+f"(c[0]), "+f"(c[1]), "+f"(c[2]), "+f"(c[3])
        : "r"(a[0]), "r"(a[1]), "r"(a[2]), "r"(a[3]), "r"(b0), "r"(b1));
}

// ---------------------------------------------------------------------------
// tf32 mma.sync GEMM:  C[M,N] = alpha * A[M,K] @ B[N,K]^T  (+bias) (+tf32 round)
// CTA tile 128x256, K-chunk 32, 3-stage cp.async pipeline, 256 threads,
// 8 warps each owning a 64x64 sub-tile. Batched via blockIdx.z.
// ---------------------------------------------------------------------------
constexpr int BM = 128, BN = 256, BK = 32, STAGES = 3;
constexpr int ATILE   = BM * BK * 4;            // 16 KB
constexpr int BTILE   = BN * BK * 4;            // 32 KB
constexpr int STAGE_B = ATILE + BTILE;          // 48 KB
constexpr int GEMM_SMEM = STAGES * STAGE_B + 1024;

template <bool BIAS, bool ROUND>
__global__ __launch_bounds__(256, 1)
void gemm_tc(const float* __restrict__ Ag, const float* __restrict__ Bg,
             float* __restrict__ Cg, const float* __restrict__ bias,
             int lda, int ldb, int ldc,
             long long sA, long long sB, long long sC,
             int K, float alpha)
{
    extern __shared__ char smem_raw[];
    const uint32_t sb = (s2u(smem_raw) + 1023u) & ~1023u;

    const int tid = threadIdx.x, lane = tid & 31, wid = tid >> 5;
    const int wm = wid & 1;          // 0..1 : 64-row slab
    const int wn = wid >> 1;         // 0..3 : 64-col slab
    const int m0 = blockIdx.y * BM, n0 = blockIdx.x * BN;

    const float* A = Ag + (size_t)blockIdx.z * sA;
    const float* B = Bg + (size_t)blockIdx.z * sB;
    float*       C = Cg + (size_t)blockIdx.z * sC;
    const int nk = K / BK;

    // ---- loader mapping: row=r0+32i, kq = 16B chunk within 128B row ----
    const int r0 = tid >> 3;                   // 0..31
    const int kq = tid & 7;
    const uint32_t sxor = (uint32_t)((r0 & 7) << 4);
    const uint32_t scol = ((uint32_t)(kq * 16)) ^ sxor;

    const float* Arow = A + (size_t)(m0 + r0) * lda + kq * 4;
    const float* Brow = B + (size_t)(n0 + r0) * ldb + kq * 4;

    // ---- fragment-load mapping (ldmatrix) ----
    const int  rbase = lane & 15;
    const uint32_t xorv = (uint32_t)((lane & 7) << 4);
    const uint32_t kq16 = (uint32_t)((lane >> 4) << 4);   // 0 or 16 bytes

    float acc[4][8][4];
#pragma unroll
    for (int a = 0; a < 4; a++)
#pragma unroll
        for (int b = 0; b < 8; b++)
#pragma unroll
            for (int c = 0; c < 4; c++) acc[a][b][c] = 0.0f;

#define LOAD_STAGE(s, kc)                                                      \
    do {                                                                       \
        const uint32_t ab = sb + (s) * STAGE_B;                                \
        const float* ap = Arow + (size_t)(kc) * BK;                            \
        const float* bp = Brow + (size_t)(kc) * BK;                            \
        _Pragma("unroll")                                                      \
        for (int i = 0; i < 4; i++)                                            \
            cpa16(ab + (uint32_t)((r0 + 32 * i) * 128) + scol,                 \
                  ap + (size_t)(32 * i) * lda);                                \
        _Pragma("unroll")                                                      \
        for (int i = 0; i < 8; i++)                                            \
            cpa16(ab + ATILE + (uint32_t)((r0 + 32 * i) * 128) + scol,         \
                  bp + (size_t)(32 * i) * ldb);                                \
    } while (0)

    // prologue: stages 0,1
    LOAD_STAGE(0, 0);
    asm volatile("cp.async.commit_group;");
    LOAD_STAGE(1, 1);
    asm volatile("cp.async.commit_group;");

    for (int kc = 0; kc < nk; kc++) {
        asm volatile("cp.async.wait_group 1;");
        __syncthreads();                       // single barrier per iteration

        if (kc + 2 < nk) {
            const int s = (kc + 2) % STAGES;
            LOAD_STAGE(s, kc + 2);
        }
        asm volatile("cp.async.commit_group;");

        // ---- compute on stage kc%STAGES ----
        const uint32_t stg = sb + (kc % STAGES) * STAGE_B;
        const uint32_t aB = stg + (uint32_t)((wm * 64 + rbase) * 128);
        const uint32_t bB = stg + ATILE + (uint32_t)((wn * 64 + rbase) * 128);
#pragma unroll
        for (int ks = 0; ks < 4; ks++) {
            const uint32_t kt = ((uint32_t)(ks * 32) + kq16) ^ xorv;
            uint32_t af[4][4], bf[4][4];
#pragma unroll
            for (int mt = 0; mt < 4; mt++) ldsm4(af[mt], aB + mt * 16 * 128 + kt);
#pragma unroll
            for (int bp = 0; bp < 4; bp++) ldsm4(bf[bp], bB + bp * 16 * 128 + kt);
#pragma unroll
            for (int mt = 0; mt < 4; mt++)
#pragma unroll
                for (int bp = 0; bp < 4; bp++) {
                    mma8(acc[mt][2 * bp + 0], af[mt], bf[bp][0], bf[bp][2]);
                    mma8(acc[mt][2 * bp + 1], af[mt], bf[bp][1], bf[bp][3]);
                }
        }
    }
#undef LOAD_STAGE

    // ---- epilogue ----
    const int g = lane >> 2, tg = lane & 3;
#pragma unroll
    for (int mt = 0; mt < 4; mt++) {
        const size_t rw0 = (size_t)(m0 + wm * 64 + mt * 16 + g) * ldc;
        const size_t rw1 = rw0 + (size_t)8 * ldc;
#pragma unroll
        for (int nn = 0; nn < 8; nn++) {
            const int col = n0 + wn * 64 + nn * 8 + tg * 2;
            float2 v0, v1;
            v0.x = acc[mt][nn][0] * alpha;
            v0.y = acc[mt][nn][1] * alpha;
            v1.x = acc[mt][nn][2] * alpha;
            v1.y = acc[mt][nn][3] * alpha;
            if (BIAS) {
                const float b0 = bias[col], b1 = bias[col + 1];
                v0.x += b0; v0.y += b1;
                v1.x += b0; v1.y += b1;
            }
            if (ROUND) {
                v0.x = tf32r(v0.x); v0.y = tf32r(v0.y);
                v1.x = tf32r(v1.x); v1.y = tf32r(v1.y);
            }
            *(float2*)(C + rw0 + col) = v0;
            *(float2*)(C + rw1 + col) = v1;
        }
    }
}

// ---------------------------------------------------------------------------
// round-to-tf32 copy (for x)
// ---------------------------------------------------------------------------
__global__ void round_copy4(const float4* __restrict__ in, float4* __restrict__ out, int n4)
{
    for (int i = blockIdx.x * blockDim.x + threadIdx.x; i < n4; i += gridDim.x * blockDim.x) {
        float4 v = in[i];
        v.x = tf32r(v.x); v.y = tf32r(v.y); v.z = tf32r(v.z); v.w = tf32r(v.w);
        out[i] = v;
    }
}

// ---------------------------------------------------------------------------
// Tiled transpose with tf32 rounding:  dst[c][r] = round(src[r][c])
// grid (C/32, R/32, batch), block (32,8)
// ---------------------------------------------------------------------------
__global__ void transpose_round_k(const float* __restrict__ src, float* __restrict__ dst,
                                  int ldS, int ldD, long long sS, long long sD)
{
    __shared__ float t[32][33];
    src += (size_t)blockIdx.z * sS;
    dst += (size_t)blockIdx.z * sD;
    const int c0 = blockIdx.x * 32, r0 = blockIdx.y * 32;
    const int tx = threadIdx.x, ty = threadIdx.y;
#pragma unroll
    for (int i = 0; i < 32; i += 8)
        t[ty + i][tx] = src[(size_t)(r0 + ty + i) * ldS + c0 + tx];
    __syncthreads();
#pragma unroll
    for (int i = 0; i < 32; i += 8)
        dst[(size_t)(c0 + ty + i) * ldD + r0 + tx] = tf32r(t[tx][ty + i]);
}

// ---------------------------------------------------------------------------
// Fused dual softmax with mask-fill (in place), tf32-rounded output.
// One CTA per (b,q) row of 2048; 256 threads, 8 values each.
// ---------------------------------------------------------------------------
__global__ __launch_bounds__(256)
void dual_softmax_k(float* __restrict__ scores, const int* __restrict__ mask)
{
    const long long row = blockIdx.x;
    float* s = scores + row * 2048;
    const int* mk = mask + row * 2048;
    const int tid = threadIdx.x;

    float v[8];
    int m[8];
#pragma unroll
    for (int i = 0; i < 8; ++i) {
        v[i] = s[tid + (i << 8)];
        m[i] = mk[tid + (i << 8)];
    }

    __shared__ float sred[8];

    // softmax 1: max
    float x = -3.0e38f;
#pragma unroll
    for (int i = 0; i < 8; ++i) x = fmaxf(x, v[i]);
#pragma unroll
    for (int o = 16; o > 0; o >>= 1) x = fmaxf(x, __shfl_xor_sync(0xffffffffu, x, o));
    if ((tid & 31) == 0) sred[tid >> 5] = x;
    __syncthreads();
    if (tid == 0) {
        float y = sred[0];
#pragma unroll
        for (int w = 1; w < 8; ++w) y = fmaxf(y, sred[w]);
        sred[0] = y;
    }
    __syncthreads();
    const float m1 = sred[0];
    __syncthreads();

    // softmax 1: exp + sum
    float su = 0.0f;
#pragma unroll
    for (int i = 0; i < 8; ++i) {
        v[i] = __expf(v[i] - m1);
        su += v[i];
    }
#pragma unroll
    for (int o = 16; o > 0; o >>= 1) su += __shfl_xor_sync(0xffffffffu, su, o);
    if ((tid & 31) == 0) sred[tid >> 5] = su;
    __syncthreads();
    if (tid == 0) {
        float y = 0.0f;
#pragma unroll
        for (int w = 0; w < 8; ++w) y += sred[w];
        sred[0] = y;
    }
    __syncthreads();
    const float inv1 = 1.0f / sred[0];
    __syncthreads();

#pragma unroll
    for (int i = 0; i < 8; ++i) v[i] *= inv1;

    // softmax 2: masked max
    float x2 = -1.0e30f;
#pragma unroll
    for (int i = 0; i < 8; ++i)
        if (m[i]) x2 = fmaxf(x2, v[i]);
#pragma unroll
    for (int o = 16; o > 0; o >>= 1) x2 = fmaxf(x2, __shfl_xor_sync(0xffffffffu, x2, o));
    if ((tid & 31) == 0) sred[tid >> 5] = x2;
    __syncthreads();
    if (tid == 0) {
        float y = sred[0];
#pragma unroll
        for (int w = 1; w < 8; ++w) y = fmaxf(y, sred[w]);
        sred[0] = y;
    }
    __syncthreads();
    const float m2 = sred[0];
    __syncthreads();

    if (m2 < -1.0e29f) {
        const float u = tf32r(1.0f / 2048.0f);
#pragma unroll
        for (int i = 0; i < 8; ++i) s[tid + (i << 8)] = u;
        return;
    }

    // softmax 2: masked exp + sum
    float su2 = 0.0f;
#pragma unroll
    for (int i = 0; i < 8; ++i) {
        const float e = m[i] ? __expf(v[i] - m2) : 0.0f;
        v[i] = e;
        su2 += e;
    }
#pragma unroll
    for (int o = 16; o > 0; o >>= 1) su2 += __shfl_xor_sync(0xffffffffu, su2, o);
    if ((tid & 31) == 0) sred[tid >> 5] = su2;
    __syncthreads();
    if (tid == 0) {
        float y = 0.0f;
#pragma unroll
        for (int w = 0; w < 8; ++w) y += sred[w];
        sred[0] = y;
    }
    __syncthreads();
    const float inv2 = 1.0f / sred[0];

#pragma unroll
    for (int i = 0; i < 8; ++i) s[tid + (i << 8)] = tf32r(v[i] * inv2);
}

// ---------------------------------------------------------------------------
// Launch
// ---------------------------------------------------------------------------
extern "C" void kernel_launch(void* const* d_in, const int* in_sizes, int n_in,
                              void* d_out, int out_size)
{
    (void)in_sizes; (void)n_in; (void)out_size;

    const float* x     = (const float*)d_in[0];
    const int*   mask  = (const int*)d_in[1];
    const float* W_qkv = (const float*)d_in[2];
    const float* b_qkv = (const float*)d_in[3];
    const float* W_out = (const float*)d_in[4];
    const float* b_out = (const float*)d_in[5];
    float* out = (float*)d_out;

    float *xr, *qkv, *scores, *att, *vT, *wqkvT, *woutT;
    cudaGetSymbolAddress((void**)&xr, g_xr);
    cudaGetSymbolAddress((void**)&qkv, g_qkv);
    cudaGetSymbolAddress((void**)&scores, g_scores);
    cudaGetSymbolAddress((void**)&att, g_att);
    cudaGetSymbolAddress((void**)&vT, g_vT);
    cudaGetSymbolAddress((void**)&wqkvT, g_wqkvT);
    cudaGetSymbolAddress((void**)&woutT, g_woutT);

    cudaFuncSetAttribute(gemm_tc<true,  true >, cudaFuncAttributeMaxDynamicSharedMemorySize, GEMM_SMEM);
    cudaFuncSetAttribute(gemm_tc<false, false>, cudaFuncAttributeMaxDynamicSharedMemorySize, GEMM_SMEM);
    cudaFuncSetAttribute(gemm_tc<false, true >, cudaFuncAttributeMaxDynamicSharedMemorySize, GEMM_SMEM);
    cudaFuncSetAttribute(gemm_tc<true,  false>, cudaFuncAttributeMaxDynamicSharedMemorySize, GEMM_SMEM);

    const int ROWS = BBATCH * SEQ;                     // 16384
    const long long sQKV = (long long)SEQ * 3 * DIM;
    const long long sSC  = (long long)SEQ * SEQ;
    const long long sAT  = (long long)SEQ * DIM;
    const long long sVT  = (long long)DIM * SEQ;

    // 0) round x to tf32
    round_copy4<<<4096, 256>>>((const float4*)x, (float4*)xr, ROWS * DIM / 4);

    // 0b) transpose + round weights
    transpose_round_k<<<dim3(3 * DIM / 32, DIM / 32, 1), dim3(32, 8)>>>(
        W_qkv, wqkvT, 3 * DIM, DIM, 0, 0);
    transpose_round_k<<<dim3(DIM / 32, DIM / 32, 1), dim3(32, 8)>>>(
        W_out, woutT, DIM, DIM, 0, 0);

    // 1) qkv = x @ W_qkv + b_qkv  (rounded)
    gemm_tc<true, true><<<dim3(3 * DIM / BN, ROWS / BM, 1), 256, GEMM_SMEM>>>(
        xr, wqkvT, qkv, b_qkv, DIM, DIM, 3 * DIM, 0, 0, 0, DIM, 1.0f);

    // 1b) V^T per batch
    transpose_round_k<<<dim3(DIM / 32, SEQ / 32, BBATCH), dim3(32, 8)>>>(
        qkv + 2 * DIM, vT, 3 * DIM, SEQ, sQKV, sVT);

    // 2) scores = Q @ K^T / 32
    gemm_tc<false, false><<<dim3(SEQ / BN, SEQ / BM, BBATCH), 256, GEMM_SMEM>>>(
        qkv, qkv + DIM, scores, nullptr, 3 * DIM, 3 * DIM, SEQ,
        sQKV, sQKV, sSC, DIM, 0.03125f);

    // 3) dual softmax + mask (in place, rounded)
    dual_softmax_k<<<ROWS, 256>>>(scores, mask);

    // 4) att = w @ V  (rounded)
    gemm_tc<false, true><<<dim3(DIM / BN, SEQ / BM, BBATCH), 256, GEMM_SMEM>>>(
        scores, vT, att, nullptr, SEQ, SEQ, DIM,
        sSC, sVT, sAT, SEQ, 1.0f);

    // 5) out = att @ W_out + b_out
    gemm_tc<true, false><<<dim3(DIM / BN, ROWS / BM, 1), 256, GEMM_SMEM>>>(
        att, woutT, out, b_out, DIM, DIM, DIM, 0, 0, 0, DIM, 1.0f);
}

// round 7
// speedup vs baseline: 1.1091x; 1.1091x over previous
#include <cuda_runtime.h>
#include <cstdint>
#include <math.h>

// ---------------------------------------------------------------------------
// Problem sizes
// ---------------------------------------------------------------------------
constexpr int BBATCH = 8;
constexpr int SEQ    = 2048;
constexpr int DIM    = 1024;

// ---------------------------------------------------------------------------
// Scratch (static device globals — allocation-guard safe)
// ---------------------------------------------------------------------------
__device__ float g_xr    [(size_t)BBATCH * SEQ * DIM];      //  64 MB rounded x
__device__ float g_qkv   [(size_t)BBATCH * SEQ * 3 * DIM];  // 192 MB
__device__ float g_scores[(size_t)BBATCH * SEQ * SEQ];      // 128 MB
__device__ float g_att   [(size_t)BBATCH * SEQ * DIM];      //  64 MB
__device__ float g_vT    [(size_t)BBATCH * DIM * SEQ];      //  64 MB V^T per batch
__device__ float g_wqkvT [(size_t)3 * DIM * DIM];           //  12 MB
__device__ float g_woutT [(size_t)DIM * DIM];               //   4 MB

// ---------------------------------------------------------------------------
// Helpers (all baseline PTX — nothing sm_103a-gated)
// ---------------------------------------------------------------------------
__device__ __forceinline__ float tf32r(float x) {           // round-to-nearest tf32
    uint32_t u;
    asm("cvt.rna.tf32.f32 %0, %1;" : "=r"(u) : "f"(x));
    return __uint_as_float(u);
}

__device__ __forceinline__ uint32_t s2u(const void* p) {
    uint32_t a;
    asm("{ .reg .u64 t; cvta.to.shared.u64 t, %1; cvt.u32.u64 %0, t; }"
        : "=r"(a) : "l"(p));
    return a;
}

__device__ __forceinline__ void cpa16(uint32_t s, const void* g) {
    asm volatile("cp.async.cg.shared.global [%0], [%1], 16;" :: "r"(s), "l"(g));
}

__device__ __forceinline__ void ldsm4(uint32_t r[4], uint32_t addr) {
    asm volatile("ldmatrix.sync.aligned.m8n8.x4.shared.b16 {%0,%1,%2,%3}, [%4];"
                 : "=r"(r[0]), "=r"(r[1]), "=r"(r[2]), "=r"(r[3]) : "r"(addr));
}

__device__ __forceinline__ void mma8(float c[4], const uint32_t a[4],
                                     uint32_t b0, uint32_t b1) {
    asm volatile(
        "mma.sync.aligned.m16n8k8.row.col.f32.tf32.tf32.f32 "
        "{%0,%1,%2,%3}, {%4,%5,%6,%7}, {%8,%9}, {%0,%1,%2,%3};"
        : "+f"(c[0]), "+f"(c[1]), "+f"(c[2]), "+f"(c[3])
        : "r"(a[0]), "r"(a[1]), "r"(a[2]), "r"(a[3]), "r"(b0), "r"(b1));
}

// ---------------------------------------------------------------------------
// tf32 mma.sync GEMM:  C[M,N] = alpha * A[M,K] @ B[N,K]^T  (+bias) (+tf32 round)
// CTA tile 128x128, K-chunk 32, 3-stage cp.async pipeline, 128 threads,
// 4 warps each owning a 64x64 sub-tile (2x2). 2 CTAs/SM. Batched via blockIdx.z.
// ---------------------------------------------------------------------------
constexpr int BM = 128, BN = 128, BK = 32, STAGES = 3;
constexpr int ATILE   = BM * BK * 4;            // 16 KB
constexpr int BTILE   = BN * BK * 4;            // 16 KB
constexpr int STAGE_B = ATILE + BTILE;          // 32 KB
constexpr int GEMM_SMEM = STAGES * STAGE_B + 1024;   // 97 KB

template <bool BIAS, bool ROUND>
__global__ __launch_bounds__(128, 2)
void gemm_tc(const float* __restrict__ Ag, const float* __restrict__ Bg,
             float* __restrict__ Cg, const float* __restrict__ bias,
             int lda, int ldb, int ldc,
             long long sA, long long sB, long long sC,
             int K, float alpha)
{
    extern __shared__ char smem_raw[];
    const uint32_t sb = (s2u(smem_raw) + 1023u) & ~1023u;

    const int tid = threadIdx.x, lane = tid & 31, wid = tid >> 5;
    const int wm = wid & 1;          // 0..1 : 64-row slab
    const int wn = wid >> 1;         // 0..1 : 64-col slab
    const int m0 = blockIdx.y * BM, n0 = blockIdx.x * BN;

    const float* A = Ag + (size_t)blockIdx.z * sA;
    const float* B = Bg + (size_t)blockIdx.z * sB;
    float*       C = Cg + (size_t)blockIdx.z * sC;
    const int nk = K / BK;

    // ---- loader mapping: 128 threads, rows r0+16i, kq = 16B chunk in 128B row
    const int r0 = tid >> 3;                   // 0..15
    const int kq = tid & 7;
    const uint32_t scol = ((uint32_t)(kq * 16)) ^ ((uint32_t)((r0 & 7) << 4));

    const float* Arow = A + (size_t)(m0 + r0) * lda + kq * 4;
    const float* Brow = B + (size_t)(n0 + r0) * ldb + kq * 4;

    // ---- fragment-load mapping (ldmatrix) ----
    const int  rbase = lane & 15;
    const uint32_t xorv = (uint32_t)((lane & 7) << 4);
    const uint32_t kq16 = (uint32_t)((lane >> 4) << 4);   // 0 or 16 bytes

    float acc[4][8][4];
#pragma unroll
    for (int a = 0; a < 4; a++)
#pragma unroll
        for (int b = 0; b < 8; b++)
#pragma unroll
            for (int c = 0; c < 4; c++) acc[a][b][c] = 0.0f;

#define LOAD_STAGE(s, kc)                                                      \
    do {                                                                       \
        const uint32_t ab = sb + (s) * STAGE_B;                                \
        const float* ap = Arow + (size_t)(kc) * BK;                            \
        const float* bp = Brow + (size_t)(kc) * BK;                            \
        _Pragma("unroll")                                                      \
        for (int i = 0; i < 8; i++) {                                          \
            cpa16(ab + (uint32_t)((r0 + 16 * i) * 128) + scol,                 \
                  ap + (size_t)(16 * i) * lda);                                \
            cpa16(ab + ATILE + (uint32_t)((r0 + 16 * i) * 128) + scol,         \
                  bp + (size_t)(16 * i) * ldb);                                \
        }                                                                      \
    } while (0)

    // prologue: stages 0,1
    LOAD_STAGE(0, 0);
    asm volatile("cp.async.commit_group;");
    LOAD_STAGE(1, 1);
    asm volatile("cp.async.commit_group;");

    for (int kc = 0; kc < nk; kc++) {
        asm volatile("cp.async.wait_group 1;");
        __syncthreads();                       // single barrier per iteration

        if (kc + 2 < nk) {
            const int s = (kc + 2) % STAGES;
            LOAD_STAGE(s, kc + 2);
        }
        asm volatile("cp.async.commit_group;");

        // ---- compute on stage kc%STAGES ----
        const uint32_t stg = sb + (kc % STAGES) * STAGE_B;
        const uint32_t aB = stg + (uint32_t)((wm * 64 + rbase) * 128);
        const uint32_t bB = stg + ATILE + (uint32_t)((wn * 64 + rbase) * 128);
#pragma unroll
        for (int ks = 0; ks < 4; ks++) {
            const uint32_t kt = ((uint32_t)(ks * 32) + kq16) ^ xorv;
            uint32_t af[4][4], bf[4][4];
#pragma unroll
            for (int mt = 0; mt < 4; mt++) ldsm4(af[mt], aB + mt * 16 * 128 + kt);
#pragma unroll
            for (int bp = 0; bp < 4; bp++) ldsm4(bf[bp], bB + bp * 16 * 128 + kt);
#pragma unroll
            for (int mt = 0; mt < 4; mt++)
#pragma unroll
                for (int bp = 0; bp < 4; bp++) {
                    mma8(acc[mt][2 * bp + 0], af[mt], bf[bp][0], bf[bp][2]);
                    mma8(acc[mt][2 * bp + 1], af[mt], bf[bp][1], bf[bp][3]);
                }
        }
    }
#undef LOAD_STAGE

    // ---- epilogue ----
    const int g = lane >> 2, tg = lane & 3;
#pragma unroll
    for (int mt = 0; mt < 4; mt++) {
        const size_t rw0 = (size_t)(m0 + wm * 64 + mt * 16 + g) * ldc;
        const size_t rw1 = rw0 + (size_t)8 * ldc;
#pragma unroll
        for (int nn = 0; nn < 8; nn++) {
            const int col = n0 + wn * 64 + nn * 8 + tg * 2;
            float2 v0, v1;
            v0.x = acc[mt][nn][0] * alpha;
            v0.y = acc[mt][nn][1] * alpha;
            v1.x = acc[mt][nn][2] * alpha;
            v1.y = acc[mt][nn][3] * alpha;
            if (BIAS) {
                const float b0 = bias[col], b1 = bias[col + 1];
                v0.x += b0; v0.y += b1;
                v1.x += b0; v1.y += b1;
            }
            if (ROUND) {
                v0.x = tf32r(v0.x); v0.y = tf32r(v0.y);
                v1.x = tf32r(v1.x); v1.y = tf32r(v1.y);
            }
            *(float2*)(C + rw0 + col) = v0;
            *(float2*)(C + rw1 + col) = v1;
        }
    }
}

// ---------------------------------------------------------------------------
// round-to-tf32 copy (for x)
// ---------------------------------------------------------------------------
__global__ void round_copy4(const float4* __restrict__ in, float4* __restrict__ out, int n4)
{
    for (int i = blockIdx.x * blockDim.x + threadIdx.x; i < n4; i += gridDim.x * blockDim.x) {
        float4 v = in[i];
        v.x = tf32r(v.x); v.y = tf32r(v.y); v.z = tf32r(v.z); v.w = tf32r(v.w);
        out[i] = v;
    }
}

// ---------------------------------------------------------------------------
// Tiled transpose with tf32 rounding:  dst[c][r] = round(src[r][c])
// grid (C/32, R/32, batch), block (32,8)
// ---------------------------------------------------------------------------
__global__ void transpose_round_k(const float* __restrict__ src, float* __restrict__ dst,
                                  int ldS, int ldD, long long sS, long long sD)
{
    __shared__ float t[32][33];
    src += (size_t)blockIdx.z * sS;
    dst += (size_t)blockIdx.z * sD;
    const int c0 = blockIdx.x * 32, r0 = blockIdx.y * 32;
    const int tx = threadIdx.x, ty = threadIdx.y;
#pragma unroll
    for (int i = 0; i < 32; i += 8)
        t[ty + i][tx] = src[(size_t)(r0 + ty + i) * ldS + c0 + tx];
    __syncthreads();
#pragma unroll
    for (int i = 0; i < 32; i += 8)
        dst[(size_t)(c0 + ty + i) * ldD + r0 + tx] = tf32r(t[tx][ty + i]);
}

// ---------------------------------------------------------------------------
// Fused dual softmax with mask-fill (in place), tf32-rounded output.
// One CTA per (b,q) row of 2048; 256 threads, 8 values each.
// ---------------------------------------------------------------------------
__global__ __launch_bounds__(256)
void dual_softmax_k(float* __restrict__ scores, const int* __restrict__ mask)
{
    const long long row = blockIdx.x;
    float* s = scores + row * 2048;
    const int* mk = mask + row * 2048;
    const int tid = threadIdx.x;

    float v[8];
    int m[8];
#pragma unroll
    for (int i = 0; i < 8; ++i) {
        v[i] = s[tid + (i << 8)];
        m[i] = mk[tid + (i << 8)];
    }

    __shared__ float sred[8];

    // softmax 1: max
    float x = -3.0e38f;
#pragma unroll
    for (int i = 0; i < 8; ++i) x = fmaxf(x, v[i]);
#pragma unroll
    for (int o = 16; o > 0; o >>= 1) x = fmaxf(x, __shfl_xor_sync(0xffffffffu, x, o));
    if ((tid & 31) == 0) sred[tid >> 5] = x;
    __syncthreads();
    if (tid == 0) {
        float y = sred[0];
#pragma unroll
        for (int w = 1; w < 8; ++w) y = fmaxf(y, sred[w]);
        sred[0] = y;
    }
    __syncthreads();
    const float m1 = sred[0];
    __syncthreads();

    // softmax 1: exp + sum
    float su = 0.0f;
#pragma unroll
    for (int i = 0; i < 8; ++i) {
        v[i] = __expf(v[i] - m1);
        su += v[i];
    }
#pragma unroll
    for (int o = 16; o > 0; o >>= 1) su += __shfl_xor_sync(0xffffffffu, su, o);
    if ((tid & 31) == 0) sred[tid >> 5] = su;
    __syncthreads();
    if (tid == 0) {
        float y = 0.0f;
#pragma unroll
        for (int w = 0; w < 8; ++w) y += sred[w];
        sred[0] = y;
    }
    __syncthreads();
    const float inv1 = 1.0f / sred[0];
    __syncthreads();

#pragma unroll
    for (int i = 0; i < 8; ++i) v[i] *= inv1;

    // softmax 2: masked max
    float x2 = -1.0e30f;
#pragma unroll
    for (int i = 0; i < 8; ++i)
        if (m[i]) x2 = fmaxf(x2, v[i]);
#pragma unroll
    for (int o = 16; o > 0; o >>= 1) x2 = fmaxf(x2, __shfl_xor_sync(0xffffffffu, x2, o));
    if ((tid & 31) == 0) sred[tid >> 5] = x2;
    __syncthreads();
    if (tid == 0) {
        float y = sred[0];
#pragma unroll
        for (int w = 1; w < 8; ++w) y = fmaxf(y, sred[w]);
        sred[0] = y;
    }
    __syncthreads();
    const float m2 = sred[0];
    __syncthreads();

    if (m2 < -1.0e29f) {
        const float u = tf32r(1.0f / 2048.0f);
#pragma unroll
        for (int i = 0; i < 8; ++i) s[tid + (i << 8)] = u;
        return;
    }

    // softmax 2: masked exp + sum
    float su2 = 0.0f;
#pragma unroll
    for (int i = 0; i < 8; ++i) {
        const float e = m[i] ? __expf(v[i] - m2) : 0.0f;
        v[i] = e;
        su2 += e;
    }
#pragma unroll
    for (int o = 16; o > 0; o >>= 1) su2 += __shfl_xor_sync(0xffffffffu, su2, o);
    if ((tid & 31) == 0) sred[tid >> 5] = su2;
    __syncthreads();
    if (tid == 0) {
        float y = 0.0f;
#pragma unroll
        for (int w = 0; w < 8; ++w) y += sred[w];
        sred[0] = y;
    }
    __syncthreads();
    const float inv2 = 1.0f / sred[0];

#pragma unroll
    for (int i = 0; i < 8; ++i) s[tid + (i << 8)] = tf32r(v[i] * inv2);
}

// ---------------------------------------------------------------------------
// Launch
// ---------------------------------------------------------------------------
extern "C" void kernel_launch(void* const* d_in, const int* in_sizes, int n_in,
                              void* d_out, int out_size)
{
    (void)in_sizes; (void)n_in; (void)out_size;

    const float* x     = (const float*)d_in[0];
    const int*   mask  = (const int*)d_in[1];
    const float* W_qkv = (const float*)d_in[2];
    const float* b_qkv = (const float*)d_in[3];
    const float* W_out = (const float*)d_in[4];
    const float* b_out = (const float*)d_in[5];
    float* out = (float*)d_out;

    float *xr, *qkv, *scores, *att, *vT, *wqkvT, *woutT;
    cudaGetSymbolAddress((void**)&xr, g_xr);
    cudaGetSymbolAddress((void**)&qkv, g_qkv);
    cudaGetSymbolAddress((void**)&scores, g_scores);
    cudaGetSymbolAddress((void**)&att, g_att);
    cudaGetSymbolAddress((void**)&vT, g_vT);
    cudaGetSymbolAddress((void**)&wqkvT, g_wqkvT);
    cudaGetSymbolAddress((void**)&woutT, g_woutT);

    cudaFuncSetAttribute(gemm_tc<true,  true >, cudaFuncAttributeMaxDynamicSharedMemorySize, GEMM_SMEM);
    cudaFuncSetAttribute(gemm_tc<false, false>, cudaFuncAttributeMaxDynamicSharedMemorySize, GEMM_SMEM);
    cudaFuncSetAttribute(gemm_tc<false, true >, cudaFuncAttributeMaxDynamicSharedMemorySize, GEMM_SMEM);
    cudaFuncSetAttribute(gemm_tc<true,  false>, cudaFuncAttributeMaxDynamicSharedMemorySize, GEMM_SMEM);

    const int ROWS = BBATCH * SEQ;                     // 16384
    const long long sQKV = (long long)SEQ * 3 * DIM;
    const long long sSC  = (long long)SEQ * SEQ;
    const long long sAT  = (long long)SEQ * DIM;
    const long long sVT  = (long long)DIM * SEQ;

    // 0) round x to tf32
    round_copy4<<<4096, 256>>>((const float4*)x, (float4*)xr, ROWS * DIM / 4);

    // 0b) transpose + round weights
    transpose_round_k<<<dim3(3 * DIM / 32, DIM / 32, 1), dim3(32, 8)>>>(
        W_qkv, wqkvT, 3 * DIM, DIM, 0, 0);
    transpose_round_k<<<dim3(DIM / 32, DIM / 32, 1), dim3(32, 8)>>>(
        W_out, woutT, DIM, DIM, 0, 0);

    // 1) qkv = x @ W_qkv + b_qkv  (rounded)
    gemm_tc<true, true><<<dim3(3 * DIM / BN, ROWS / BM, 1), 128, GEMM_SMEM>>>(
        xr, wqkvT, qkv, b_qkv, DIM, DIM, 3 * DIM, 0, 0, 0, DIM, 1.0f);

    // 1b) V^T per batch
    transpose_round_k<<<dim3(DIM / 32, SEQ / 32, BBATCH), dim3(32, 8)>>>(
        qkv + 2 * DIM, vT, 3 * DIM, SEQ, sQKV, sVT);

    // 2) scores = Q @ K^T / 32
    gemm_tc<false, false><<<dim3(SEQ / BN, SEQ / BM, BBATCH), 128, GEMM_SMEM>>>(
        qkv, qkv + DIM, scores, nullptr, 3 * DIM, 3 * DIM, SEQ,
        sQKV, sQKV, sSC, DIM, 0.03125f);

    // 3) dual softmax + mask (in place, rounded)
    dual_softmax_k<<<ROWS, 256>>>(scores, mask);

    // 4) att = w @ V  (rounded)
    gemm_tc<false, true><<<dim3(DIM / BN, SEQ / BM, BBATCH), 128, GEMM_SMEM>>>(
        scores, vT, att, nullptr, SEQ, SEQ, DIM,
        sSC, sVT, sAT, SEQ, 1.0f);

    // 5) out = att @ W_out + b_out
    gemm_tc<true, false><<<dim3(DIM / BN, ROWS / BM, 1), 128, GEMM_SMEM>>>(
        att, woutT, out, b_out, DIM, DIM, DIM, 0, 0, 0, DIM, 1.0f);
}

// round 9
// speedup vs baseline: 1.3291x; 1.1984x over previous
#include <cuda_runtime.h>
#include <cuda_fp16.h>
#include <cstdint>
#include <math.h>

// ---------------------------------------------------------------------------
// Problem sizes
// ---------------------------------------------------------------------------
constexpr int BBATCH = 8;
constexpr int SEQ    = 2048;
constexpr int DIM    = 1024;

// ---------------------------------------------------------------------------
// Scratch (static device globals — allocation-guard safe)
// ---------------------------------------------------------------------------
__device__ __half g_xh    [(size_t)BBATCH * SEQ * DIM];      // 32 MB
__device__ __half g_qkv   [(size_t)BBATCH * SEQ * 3 * DIM];  // 96 MB (Q|K|V fp16)
__device__ float  g_scores[(size_t)BBATCH * SEQ * SEQ];      // 128 MB fp32
__device__ __half g_w     [(size_t)BBATCH * SEQ * SEQ];      // 64 MB fp16 weights
__device__ __half g_att   [(size_t)BBATCH * SEQ * DIM];      // 32 MB
__device__ __half g_vT    [(size_t)BBATCH * DIM * SEQ];      // 32 MB
__device__ __half g_wqkvT [(size_t)3 * DIM * DIM];           //  6 MB
__device__ __half g_woutT [(size_t)DIM * DIM];               //  2 MB

// ---------------------------------------------------------------------------
// Helpers (baseline PTX only)
// ---------------------------------------------------------------------------
__device__ __forceinline__ uint32_t h2_as_u32(__half2 h) {
    uint32_t u;
    __builtin_memcpy(&u, &h, 4);
    return u;
}

__device__ __forceinline__ uint32_t s2u(const void* p) {
    uint32_t a;
    asm("{ .reg .u64 t; cvta.to.shared.u64 t, %1; cvt.u32.u64 %0, t; }"
        : "=r"(a) : "l"(p));
    return a;
}

__device__ __forceinline__ void cpa16(uint32_t s, const void* g) {
    asm volatile("cp.async.cg.shared.global [%0], [%1], 16;" :: "r"(s), "l"(g));
}

__device__ __forceinline__ void ldsm4(uint32_t r[4], uint32_t addr) {
    asm volatile("ldmatrix.sync.aligned.m8n8.x4.shared.b16 {%0,%1,%2,%3}, [%4];"
                 : "=r"(r[0]), "=r"(r[1]), "=r"(r[2]), "=r"(r[3]) : "r"(addr));
}

// fp16 MMA, fp32 accumulate: D(16x8) += A(16x16) * B(16x8)
__device__ __forceinline__ void mma16(float c[4], const uint32_t a[4],
                                      uint32_t b0, uint32_t b1) {
    asm volatile(
        "mma.sync.aligned.m16n8k16.row.col.f32.f16.f16.f32 "
        "{%0,%1,%2,%3}, {%4,%5,%6,%7}, {%8,%9}, {%0,%1,%2,%3};"
        : "+f"(c[0]), "+f"(c[1]), "+f"(c[2]), "+f"(c[3])
        : "r"(a[0]), "r"(a[1]), "r"(a[2]), "r"(a[3]), "r"(b0), "r"(b1));
}

// ---------------------------------------------------------------------------
// fp16 mma.sync GEMM:  C[M,N] = alpha * A[M,K] @ B[N,K]^T (+bias)
// A,B fp16 K-major; C fp32 or fp16 (OUTHALF). CTA 128x128, BK=64 halves
// (128B rows), 3-stage cp.async, 128 threads, 4 warps of 64x64. 2 CTAs/SM.
// ---------------------------------------------------------------------------
constexpr int BM = 128, BN = 128, BK = 64, STAGES = 3;
constexpr int ATILE   = BM * BK * 2;            // 16 KB
constexpr int BTILE   = BN * BK * 2;            // 16 KB
constexpr int STAGE_B = ATILE + BTILE;          // 32 KB
constexpr int GEMM_SMEM = STAGES * STAGE_B + 1024;   // 97 KB

template <bool BIAS, bool OUTHALF>
__global__ __launch_bounds__(128, 2)
void gemm_tc(const __half* __restrict__ Ag, const __half* __restrict__ Bg,
             void* __restrict__ Cg, const float* __restrict__ bias,
             int lda, int ldb, int ldc,
             long long sA, long long sB, long long sC,
             int K, float alpha)
{
    extern __shared__ char smem_raw[];
    const uint32_t sb = (s2u(smem_raw) + 1023u) & ~1023u;

    const int tid = threadIdx.x, lane = tid & 31, wid = tid >> 5;
    const int wm = wid & 1;          // 0..1 : 64-row slab
    const int wn = wid >> 1;         // 0..1 : 64-col slab
    const int m0 = blockIdx.y * BM, n0 = blockIdx.x * BN;

    const __half* A = Ag + (size_t)blockIdx.z * sA;
    const __half* B = Bg + (size_t)blockIdx.z * sB;
    const int nk = K / BK;

    // ---- loader: 128 threads, rows r0+16i, kq = 16B chunk within 128B row
    const int r0 = tid >> 3;                   // 0..15
    const int kq = tid & 7;
    const uint32_t scol = ((uint32_t)(kq * 16)) ^ ((uint32_t)((r0 & 7) << 4));

    const __half* Arow = A + (size_t)(m0 + r0) * lda + kq * 8;
    const __half* Brow = B + (size_t)(n0 + r0) * ldb + kq * 8;

    // ---- ldmatrix mapping ----
    const int  rbase = lane & 15;
    const uint32_t xorv = (uint32_t)((lane & 7) << 4);
    const uint32_t kq16 = (uint32_t)((lane >> 4) << 4);   // 0 or 16 bytes

    float acc[4][8][4];
#pragma unroll
    for (int a = 0; a < 4; a++)
#pragma unroll
        for (int b = 0; b < 8; b++)
#pragma unroll
            for (int c = 0; c < 4; c++) acc[a][b][c] = 0.0f;

#define LOAD_STAGE(s, kc)                                                      \
    do {                                                                       \
        const uint32_t ab = sb + (s) * STAGE_B;                                \
        const __half* ap = Arow + (size_t)(kc) * BK;                           \
        const __half* bp = Brow + (size_t)(kc) * BK;                           \
        _Pragma("unroll")                                                      \
        for (int i = 0; i < 8; i++) {                                          \
            cpa16(ab + (uint32_t)((r0 + 16 * i) * 128) + scol,                 \
                  ap + (size_t)(16 * i) * lda);                                \
            cpa16(ab + ATILE + (uint32_t)((r0 + 16 * i) * 128) + scol,         \
                  bp + (size_t)(16 * i) * ldb);                                \
        }                                                                      \
    } while (0)

    LOAD_STAGE(0, 0);
    asm volatile("cp.async.commit_group;");
    LOAD_STAGE(1, 1);
    asm volatile("cp.async.commit_group;");

    for (int kc = 0; kc < nk; kc++) {
        asm volatile("cp.async.wait_group 1;");
        __syncthreads();

        if (kc + 2 < nk) {
            const int s = (kc + 2) % STAGES;
            LOAD_STAGE(s, kc + 2);
        }
        asm volatile("cp.async.commit_group;");

        // ---- compute on stage kc%STAGES: 4 k-steps of k16 ----
        const uint32_t stg = sb + (kc % STAGES) * STAGE_B;
        const uint32_t aB = stg + (uint32_t)((wm * 64 + rbase) * 128);
        const uint32_t bB = stg + ATILE + (uint32_t)((wn * 64 + rbase) * 128);
#pragma unroll
        for (int ks = 0; ks < 4; ks++) {
            const uint32_t kt = ((uint32_t)(ks * 32) + kq16) ^ xorv;
            uint32_t af[4][4], bf[4][4];
#pragma unroll
            for (int mt = 0; mt < 4; mt++) ldsm4(af[mt], aB + mt * 16 * 128 + kt);
#pragma unroll
            for (int bp = 0; bp < 4; bp++) ldsm4(bf[bp], bB + bp * 16 * 128 + kt);
#pragma unroll
            for (int mt = 0; mt < 4; mt++)
#pragma unroll
                for (int bp = 0; bp < 4; bp++) {
                    mma16(acc[mt][2 * bp + 0], af[mt], bf[bp][0], bf[bp][2]);
                    mma16(acc[mt][2 * bp + 1], af[mt], bf[bp][1], bf[bp][3]);
                }
        }
    }
#undef LOAD_STAGE

    // ---- epilogue ----
    const int g = lane >> 2, tg = lane & 3;
#pragma unroll
    for (int mt = 0; mt < 4; mt++) {
        const size_t rw0 = (size_t)(m0 + wm * 64 + mt * 16 + g) * ldc;
        const size_t rw1 = rw0 + (size_t)8 * ldc;
#pragma unroll
        for (int nn = 0; nn < 8; nn++) {
            const int col = n0 + wn * 64 + nn * 8 + tg * 2;
            float2 v0, v1;
            v0.x = acc[mt][nn][0] * alpha;
            v0.y = acc[mt][nn][1] * alpha;
            v1.x = acc[mt][nn][2] * alpha;
            v1.y = acc[mt][nn][3] * alpha;
            if (BIAS) {
                const float b0 = bias[col], b1 = bias[col + 1];
                v0.x += b0; v0.y += b1;
                v1.x += b0; v1.y += b1;
            }
            if (OUTHALF) {
                __half* C = (__half*)Cg + (size_t)blockIdx.z * sC;
                *(__half2*)(C + rw0 + col) = __floats2half2_rn(v0.x, v0.y);
                *(__half2*)(C + rw1 + col) = __floats2half2_rn(v1.x, v1.y);
            } else {
                float* C = (float*)Cg + (size_t)blockIdx.z * sC;
                *(float2*)(C + rw0 + col) = v0;
                *(float2*)(C + rw1 + col) = v1;
            }
        }
    }
}

// ---------------------------------------------------------------------------
// fp32 -> fp16 copy (for x)
// ---------------------------------------------------------------------------
__global__ void f2h_copy(const float4* __restrict__ in, uint2* __restrict__ out, int n4)
{
    for (int i = blockIdx.x * blockDim.x + threadIdx.x; i < n4; i += gridDim.x * blockDim.x) {
        float4 v = in[i];
        uint2 o;
        o.x = h2_as_u32(__floats2half2_rn(v.x, v.y));
        o.y = h2_as_u32(__floats2half2_rn(v.z, v.w));
        out[i] = o;
    }
}

// ---------------------------------------------------------------------------
// Tiled transpose, float src -> half dst  (weights)
// ---------------------------------------------------------------------------
__global__ void transpose_f2h(const float* __restrict__ src, __half* __restrict__ dst,
                              int ldS, int ldD)
{
    __shared__ float t[32][33];
    const int c0 = blockIdx.x * 32, r0 = blockIdx.y * 32;
    const int tx = threadIdx.x, ty = threadIdx.y;
#pragma unroll
    for (int i = 0; i < 32; i += 8)
        t[ty + i][tx] = src[(size_t)(r0 + ty + i) * ldS + c0 + tx];
    __syncthreads();
#pragma unroll
    for (int i = 0; i < 32; i += 8)
        dst[(size_t)(c0 + ty + i) * ldD + r0 + tx] = __float2half_rn(t[tx][ty + i]);
}

// ---------------------------------------------------------------------------
// Tiled transpose, half src -> half dst (V^T), batched
// ---------------------------------------------------------------------------
__global__ void transpose_h2h(const __half* __restrict__ src, __half* __restrict__ dst,
                              int ldS, int ldD, long long sS, long long sD)
{
    __shared__ __half t[32][34];
    src += (size_t)blockIdx.z * sS;
    dst += (size_t)blockIdx.z * sD;
    const int c0 = blockIdx.x * 32, r0 = blockIdx.y * 32;
    const int tx = threadIdx.x, ty = threadIdx.y;
#pragma unroll
    for (int i = 0; i < 32; i += 8)
        t[ty + i][tx] = src[(size_t)(r0 + ty + i) * ldS + c0 + tx];
    __syncthreads();
#pragma unroll
    for (int i = 0; i < 32; i += 8)
        dst[(size_t)(c0 + ty + i) * ldD + r0 + tx] = t[tx][ty + i];
}

// ---------------------------------------------------------------------------
// Fused dual softmax with mask-fill: fp32 scores in, fp16 weights out.
// One CTA per (b,q) row of 2048; 256 threads, 8 values each.
// ---------------------------------------------------------------------------
__global__ __launch_bounds__(256)
void dual_softmax_k(const float* __restrict__ scores, const int* __restrict__ mask,
                    __half* __restrict__ wout)
{
    const long long row = blockIdx.x;
    const float* s = scores + row * 2048;
    const int* mk = mask + row * 2048;
    __half* o = wout + row * 2048;
    const int tid = threadIdx.x;

    float v[8];
    int m[8];
#pragma unroll
    for (int i = 0; i < 8; ++i) {
        v[i] = s[tid + (i << 8)];
        m[i] = mk[tid + (i << 8)];
    }

    __shared__ float sred[8];

    // softmax 1: max
    float x = -3.0e38f;
#pragma unroll
    for (int i = 0; i < 8; ++i) x = fmaxf(x, v[i]);
#pragma unroll
    for (int ofs = 16; ofs > 0; ofs >>= 1) x = fmaxf(x, __shfl_xor_sync(0xffffffffu, x, ofs));
    if ((tid & 31) == 0) sred[tid >> 5] = x;
    __syncthreads();
    if (tid == 0) {
        float y = sred[0];
#pragma unroll
        for (int w = 1; w < 8; ++w) y = fmaxf(y, sred[w]);
        sred[0] = y;
    }
    __syncthreads();
    const float m1 = sred[0];
    __syncthreads();

    // softmax 1: exp + sum
    float su = 0.0f;
#pragma unroll
    for (int i = 0; i < 8; ++i) {
        v[i] = __expf(v[i] - m1);
        su += v[i];
    }
#pragma unroll
    for (int ofs = 16; ofs > 0; ofs >>= 1) su += __shfl_xor_sync(0xffffffffu, su, ofs);
    if ((tid & 31) == 0) sred[tid >> 5] = su;
    __syncthreads();
    if (tid == 0) {
        float y = 0.0f;
#pragma unroll
        for (int w = 0; w < 8; ++w) y += sred[w];
        sred[0] = y;
    }
    __syncthreads();
    const float inv1 = 1.0f / sred[0];
    __syncthreads();

#pragma unroll
    for (int i = 0; i < 8; ++i) v[i] *= inv1;

    // softmax 2: masked max
    float x2 = -1.0e30f;
#pragma unroll
    for (int i = 0; i < 8; ++i)
        if (m[i]) x2 = fmaxf(x2, v[i]);
#pragma unroll
    for (int ofs = 16; ofs > 0; ofs >>= 1) x2 = fmaxf(x2, __shfl_xor_sync(0xffffffffu, x2, ofs));
    if ((tid & 31) == 0) sred[tid >> 5] = x2;
    __syncthreads();
    if (tid == 0) {
        float y = sred[0];
#pragma unroll
        for (int w = 1; w < 8; ++w) y = fmaxf(y, sred[w]);
        sred[0] = y;
    }
    __syncthreads();
    const float m2 = sred[0];
    __syncthreads();

    if (m2 < -1.0e29f) {
        const __half u = __float2half_rn(1.0f / 2048.0f);
#pragma unroll
        for (int i = 0; i < 8; ++i) o[tid + (i << 8)] = u;
        return;
    }

    // softmax 2: masked exp + sum
    float su2 = 0.0f;
#pragma unroll
    for (int i = 0; i < 8; ++i) {
        const float e = m[i] ? __expf(v[i] - m2) : 0.0f;
        v[i] = e;
        su2 += e;
    }
#pragma unroll
    for (int ofs = 16; ofs > 0; ofs >>= 1) su2 += __shfl_xor_sync(0xffffffffu, su2, ofs);
    if ((tid & 31) == 0) sred[tid >> 5] = su2;
    __syncthreads();
    if (tid == 0) {
        float y = 0.0f;
#pragma unroll
        for (int w = 0; w < 8; ++w) y += sred[w];
        sred[0] = y;
    }
    __syncthreads();
    const float inv2 = 1.0f / sred[0];

#pragma unroll
    for (int i = 0; i < 8; ++i) o[tid + (i << 8)] = __float2half_rn(v[i] * inv2);
}

// ---------------------------------------------------------------------------
// Launch
// ---------------------------------------------------------------------------
extern "C" void kernel_launch(void* const* d_in, const int* in_sizes, int n_in,
                              void* d_out, int out_size)
{
    (void)in_sizes; (void)n_in; (void)out_size;

    const float* x     = (const float*)d_in[0];
    const int*   mask  = (const int*)d_in[1];
    const float* W_qkv = (const float*)d_in[2];
    const float* b_qkv = (const float*)d_in[3];
    const float* W_out = (const float*)d_in[4];
    const float* b_out = (const float*)d_in[5];
    float* out = (float*)d_out;

    __half *xh, *qkv, *wbuf, *att, *vT, *wqkvT, *woutT;
    float *scores;
    cudaGetSymbolAddress((void**)&xh, g_xh);
    cudaGetSymbolAddress((void**)&qkv, g_qkv);
    cudaGetSymbolAddress((void**)&scores, g_scores);
    cudaGetSymbolAddress((void**)&wbuf, g_w);
    cudaGetSymbolAddress((void**)&att, g_att);
    cudaGetSymbolAddress((void**)&vT, g_vT);
    cudaGetSymbolAddress((void**)&wqkvT, g_wqkvT);
    cudaGetSymbolAddress((void**)&woutT, g_woutT);

    cudaFuncSetAttribute(gemm_tc<true,  true >, cudaFuncAttributeMaxDynamicSharedMemorySize, GEMM_SMEM);
    cudaFuncSetAttribute(gemm_tc<false, false>, cudaFuncAttributeMaxDynamicSharedMemorySize, GEMM_SMEM);
    cudaFuncSetAttribute(gemm_tc<false, true >, cudaFuncAttributeMaxDynamicSharedMemorySize, GEMM_SMEM);
    cudaFuncSetAttribute(gemm_tc<true,  false>, cudaFuncAttributeMaxDynamicSharedMemorySize, GEMM_SMEM);

    const int ROWS = BBATCH * SEQ;                     // 16384
    const long long sQKV = (long long)SEQ * 3 * DIM;
    const long long sSC  = (long long)SEQ * SEQ;
    const long long sAT  = (long long)SEQ * DIM;
    const long long sVT  = (long long)DIM * SEQ;

    // 0) x -> fp16
    f2h_copy<<<4096, 256>>>((const float4*)x, (uint2*)xh, ROWS * DIM / 4);

    // 0b) transpose weights -> fp16
    transpose_f2h<<<dim3(3 * DIM / 32, DIM / 32, 1), dim3(32, 8)>>>(
        W_qkv, wqkvT, 3 * DIM, DIM);
    transpose_f2h<<<dim3(DIM / 32, DIM / 32, 1), dim3(32, 8)>>>(
        W_out, woutT, DIM, DIM);

    // 1) qkv = x @ W_qkv + b_qkv   (fp16 out)
    gemm_tc<true, true><<<dim3(3 * DIM / BN, ROWS / BM, 1), 128, GEMM_SMEM>>>(
        xh, wqkvT, qkv, b_qkv, DIM, DIM, 3 * DIM, 0, 0, 0, DIM, 1.0f);

    // 1b) V^T per batch (fp16)
    transpose_h2h<<<dim3(DIM / 32, SEQ / 32, BBATCH), dim3(32, 8)>>>(
        qkv + 2 * DIM, vT, 3 * DIM, SEQ, sQKV, sVT);

    // 2) scores = Q @ K^T / 32   (fp32 out)
    gemm_tc<false, false><<<dim3(SEQ / BN, SEQ / BM, BBATCH), 128, GEMM_SMEM>>>(
        qkv, qkv + DIM, scores, nullptr, 3 * DIM, 3 * DIM, SEQ,
        sQKV, sQKV, sSC, DIM, 0.03125f);

    // 3) dual softmax + mask : fp32 scores -> fp16 w
    dual_softmax_k<<<ROWS, 256>>>(scores, mask, wbuf);

    // 4) att = w @ V   (fp16 out)
    gemm_tc<false, true><<<dim3(DIM / BN, SEQ / BM, BBATCH), 128, GEMM_SMEM>>>(
        wbuf, vT, att, nullptr, SEQ, SEQ, DIM,
        sSC, sVT, sAT, SEQ, 1.0f);

    // 5) out = att @ W_out + b_out  (fp32 out)
    gemm_tc<true, false><<<dim3(DIM / BN, ROWS / BM, 1), 128, GEMM_SMEM>>>(
        att, woutT, out, b_out, DIM, DIM, DIM, 0, 0, 0, DIM, 1.0f);
}

// round 11
// speedup vs baseline: 1.9853x; 1.4937x over previous
#include <cuda_runtime.h>
#include <cuda_fp16.h>
#include <cstdint>
#include <math.h>

// ---------------------------------------------------------------------------
// Problem sizes
// ---------------------------------------------------------------------------
constexpr int BBATCH = 8;
constexpr int SEQ    = 2048;
constexpr int DIM    = 1024;

// ---------------------------------------------------------------------------
// Scratch (static device globals — allocation-guard safe)
// ---------------------------------------------------------------------------
__device__ __half g_xh    [(size_t)BBATCH * SEQ * DIM];      // 32 MB
__device__ __half g_qkv   [(size_t)BBATCH * SEQ * 3 * DIM];  // 96 MB (Q|K|V fp16)
__device__ float  g_scores[(size_t)BBATCH * SEQ * SEQ];      // 128 MB fp32
__device__ __half g_w     [(size_t)BBATCH * SEQ * SEQ];      // 64 MB fp16 weights
__device__ __half g_att   [(size_t)BBATCH * SEQ * DIM];      // 32 MB
__device__ __half g_vT    [(size_t)BBATCH * DIM * SEQ];      // 32 MB
__device__ __half g_wqkvT [(size_t)3 * DIM * DIM];           //  6 MB
__device__ __half g_woutT [(size_t)DIM * DIM];               //  2 MB

// ---------------------------------------------------------------------------
// Helpers (baseline PTX only)
// ---------------------------------------------------------------------------
__device__ __forceinline__ uint32_t h2_as_u32(__half2 h) {
    uint32_t u;
    __builtin_memcpy(&u, &h, 4);
    return u;
}

__device__ __forceinline__ uint32_t s2u(const void* p) {
    uint32_t a;
    asm("{ .reg .u64 t; cvta.to.shared.u64 t, %1; cvt.u32.u64 %0, t; }"
        : "=r"(a) : "l"(p));
    return a;
}

__device__ __forceinline__ void cpa16(uint32_t s, const void* g) {
    asm volatile("cp.async.cg.shared.global [%0], [%1], 16;" :: "r"(s), "l"(g));
}

__device__ __forceinline__ void ldsm4(uint32_t r[4], uint32_t addr) {
    asm volatile("ldmatrix.sync.aligned.m8n8.x4.shared.b16 {%0,%1,%2,%3}, [%4];"
                 : "=r"(r[0]), "=r"(r[1]), "=r"(r[2]), "=r"(r[3]) : "r"(addr));
}

// fp16 MMA, fp32 accumulate: D(16x8) += A(16x16) * B(16x8)
__device__ __forceinline__ void mma16(float c[4], const uint32_t a[4],
                                      uint32_t b0, uint32_t b1) {
    asm volatile(
        "mma.sync.aligned.m16n8k16.row.col.f32.f16.f16.f32 "
        "{%0,%1,%2,%3}, {%4,%5,%6,%7}, {%8,%9}, {%0,%1,%2,%3};"
        : "+f"(c[0]), "+f"(c[1]), "+f"(c[2]), "+f"(c[3])
        : "r"(a[0]), "r"(a[1]), "r"(a[2]), "r"(a[3]), "r"(b0), "r"(b1));
}

// ---------------------------------------------------------------------------
// fp16 mma.sync GEMM:  C[M,N] = alpha * A[M,K] @ B[N,K]^T (+bias)
// A,B fp16 K-major; C fp32 or fp16 (OUTHALF). CTA tile 128x128, BK=64 halves
// (128B rows), 3-stage cp.async, 256 threads, 8 warps of 64x32. 2 CTAs/SM
// -> 16 warps/SM, 4 eligible warps per SMSP.
// ---------------------------------------------------------------------------
constexpr int BM = 128, BN = 128, BK = 64, STAGES = 3;
constexpr int ATILE   = BM * BK * 2;            // 16 KB
constexpr int BTILE   = BN * BK * 2;            // 16 KB
constexpr int STAGE_B = ATILE + BTILE;          // 32 KB
constexpr int GEMM_SMEM = STAGES * STAGE_B + 1024;   // 97 KB

template <bool BIAS, bool OUTHALF>
__global__ __launch_bounds__(256, 2)
void gemm_tc(const __half* __restrict__ Ag, const __half* __restrict__ Bg,
             void* __restrict__ Cg, const float* __restrict__ bias,
             int lda, int ldb, int ldc,
             long long sA, long long sB, long long sC,
             int K, float alpha)
{
    extern __shared__ char smem_raw[];
    const uint32_t sb = (s2u(smem_raw) + 1023u) & ~1023u;

    const int tid = threadIdx.x, lane = tid & 31, wid = tid >> 5;
    const int wm = wid & 1;          // 0..1 : 64-row slab
    const int wn = wid >> 1;         // 0..3 : 32-col slab
    const int m0 = blockIdx.y * BM, n0 = blockIdx.x * BN;

    const __half* A = Ag + (size_t)blockIdx.z * sA;
    const __half* B = Bg + (size_t)blockIdx.z * sB;
    const int nk = K / BK;

    // ---- loader: 256 threads, rows r0+32i (i<4), kq = 16B chunk in 128B row
    const int r0 = tid >> 3;                   // 0..31
    const int kq = tid & 7;
    const uint32_t scol = ((uint32_t)(kq * 16)) ^ ((uint32_t)((r0 & 7) << 4));

    const __half* Arow = A + (size_t)(m0 + r0) * lda + kq * 8;
    const __half* Brow = B + (size_t)(n0 + r0) * ldb + kq * 8;

    // ---- ldmatrix mapping ----
    const int  rbase = lane & 15;
    const uint32_t xorv = (uint32_t)((lane & 7) << 4);
    const uint32_t kq16 = (uint32_t)((lane >> 4) << 4);   // 0 or 16 bytes

    float acc[4][4][4];
#pragma unroll
    for (int a = 0; a < 4; a++)
#pragma unroll
        for (int b = 0; b < 4; b++)
#pragma unroll
            for (int c = 0; c < 4; c++) acc[a][b][c] = 0.0f;

#define LOAD_STAGE(s, kc)                                                      \
    do {                                                                       \
        const uint32_t ab = sb + (s) * STAGE_B;                                \
        const __half* ap = Arow + (size_t)(kc) * BK;                           \
        const __half* bp = Brow + (size_t)(kc) * BK;                           \
        _Pragma("unroll")                                                      \
        for (int i = 0; i < 4; i++) {                                          \
            cpa16(ab + (uint32_t)((r0 + 32 * i) * 128) + scol,                 \
                  ap + (size_t)(32 * i) * lda);                                \
            cpa16(ab + ATILE + (uint32_t)((r0 + 32 * i) * 128) + scol,         \
                  bp + (size_t)(32 * i) * ldb);                                \
        }                                                                      \
    } while (0)

    LOAD_STAGE(0, 0);
    asm volatile("cp.async.commit_group;");
    LOAD_STAGE(1, 1);
    asm volatile("cp.async.commit_group;");

    for (int kc = 0; kc < nk; kc++) {
        asm volatile("cp.async.wait_group 1;");
        __syncthreads();

        if (kc + 2 < nk) {
            const int s = (kc + 2) % STAGES;
            LOAD_STAGE(s, kc + 2);
        }
        asm volatile("cp.async.commit_group;");

        // ---- compute on stage kc%STAGES: 4 k-steps of k16 ----
        const uint32_t stg = sb + (kc % STAGES) * STAGE_B;
        const uint32_t aB = stg + (uint32_t)((wm * 64 + rbase) * 128);
        const uint32_t bB = stg + ATILE + (uint32_t)((wn * 32 + rbase) * 128);
#pragma unroll
        for (int ks = 0; ks < 4; ks++) {
            const uint32_t kt = ((uint32_t)(ks * 32) + kq16) ^ xorv;
            uint32_t af[4][4], bf[2][4];
#pragma unroll
            for (int mt = 0; mt < 4; mt++) ldsm4(af[mt], aB + mt * 16 * 128 + kt);
#pragma unroll
            for (int bp = 0; bp < 2; bp++) ldsm4(bf[bp], bB + bp * 16 * 128 + kt);
#pragma unroll
            for (int mt = 0; mt < 4; mt++)
#pragma unroll
                for (int bp = 0; bp < 2; bp++) {
                    mma16(acc[mt][2 * bp + 0], af[mt], bf[bp][0], bf[bp][2]);
                    mma16(acc[mt][2 * bp + 1], af[mt], bf[bp][1], bf[bp][3]);
                }
        }
    }
#undef LOAD_STAGE

    // ---- epilogue ----
    const int g = lane >> 2, tg = lane & 3;
#pragma unroll
    for (int mt = 0; mt < 4; mt++) {
        const size_t rw0 = (size_t)(m0 + wm * 64 + mt * 16 + g) * ldc;
        const size_t rw1 = rw0 + (size_t)8 * ldc;
#pragma unroll
        for (int nn = 0; nn < 4; nn++) {
            const int col = n0 + wn * 32 + nn * 8 + tg * 2;
            float2 v0, v1;
            v0.x = acc[mt][nn][0] * alpha;
            v0.y = acc[mt][nn][1] * alpha;
            v1.x = acc[mt][nn][2] * alpha;
            v1.y = acc[mt][nn][3] * alpha;
            if (BIAS) {
                const float b0 = bias[col], b1 = bias[col + 1];
                v0.x += b0; v0.y += b1;
                v1.x += b0; v1.y += b1;
            }
            if (OUTHALF) {
                __half* C = (__half*)Cg + (size_t)blockIdx.z * sC;
                *(__half2*)(C + rw0 + col) = __floats2half2_rn(v0.x, v0.y);
                *(__half2*)(C + rw1 + col) = __floats2half2_rn(v1.x, v1.y);
            } else {
                float* C = (float*)Cg + (size_t)blockIdx.z * sC;
                *(float2*)(C + rw0 + col) = v0;
                *(float2*)(C + rw1 + col) = v1;
            }
        }
    }
}

// ---------------------------------------------------------------------------
// fp32 -> fp16 copy (for x)
// ---------------------------------------------------------------------------
__global__ void f2h_copy(const float4* __restrict__ in, uint2* __restrict__ out, int n4)
{
    for (int i = blockIdx.x * blockDim.x + threadIdx.x; i < n4; i += gridDim.x * blockDim.x) {
        float4 v = in[i];
        uint2 o;
        o.x = h2_as_u32(__floats2half2_rn(v.x, v.y));
        o.y = h2_as_u32(__floats2half2_rn(v.z, v.w));
        out[i] = o;
    }
}

// ---------------------------------------------------------------------------
// Tiled transpose, float src -> half dst  (weights)
// ---------------------------------------------------------------------------
__global__ void transpose_f2h(const float* __restrict__ src, __half* __restrict__ dst,
                              int ldS, int ldD)
{
    __shared__ float t[32][33];
    const int c0 = blockIdx.x * 32, r0 = blockIdx.y * 32;
    const int tx = threadIdx.x, ty = threadIdx.y;
#pragma unroll
    for (int i = 0; i < 32; i += 8)
        t[ty + i][tx] = src[(size_t)(r0 + ty + i) * ldS + c0 + tx];
    __syncthreads();
#pragma unroll
    for (int i = 0; i < 32; i += 8)
        dst[(size_t)(c0 + ty + i) * ldD + r0 + tx] = __float2half_rn(t[tx][ty + i]);
}

// ---------------------------------------------------------------------------
// Tiled transpose, half src -> half dst (V^T), batched
// ---------------------------------------------------------------------------
__global__ void transpose_h2h(const __half* __restrict__ src, __half* __restrict__ dst,
                              int ldS, int ldD, long long sS, long long sD)
{
    __shared__ __half t[32][34];
    src += (size_t)blockIdx.z * sS;
    dst += (size_t)blockIdx.z * sD;
    const int c0 = blockIdx.x * 32, r0 = blockIdx.y * 32;
    const int tx = threadIdx.x, ty = threadIdx.y;
#pragma unroll
    for (int i = 0; i < 32; i += 8)
        t[ty + i][tx] = src[(size_t)(r0 + ty + i) * ldS + c0 + tx];
    __syncthreads();
#pragma unroll
    for (int i = 0; i < 32; i += 8)
        dst[(size_t)(c0 + ty + i) * ldD + r0 + tx] = t[tx][ty + i];
}

// ---------------------------------------------------------------------------
// Fused dual softmax with mask-fill: fp32 scores in, fp16 weights out.
// One CTA per (b,q) row of 2048; 256 threads, 8 values each.
// ---------------------------------------------------------------------------
__global__ __launch_bounds__(256)
void dual_softmax_k(const float* __restrict__ scores, const int* __restrict__ mask,
                    __half* __restrict__ wout)
{
    const long long row = blockIdx.x;
    const float* s = scores + row * 2048;
    const int* mk = mask + row * 2048;
    __half* o = wout + row * 2048;
    const int tid = threadIdx.x;

    float v[8];
    int m[8];
#pragma unroll
    for (int i = 0; i < 8; ++i) {
        v[i] = s[tid + (i << 8)];
        m[i] = mk[tid + (i << 8)];
    }

    __shared__ float sred[8];

    // softmax 1: max
    float x = -3.0e38f;
#pragma unroll
    for (int i = 0; i < 8; ++i) x = fmaxf(x, v[i]);
#pragma unroll
    for (int ofs = 16; ofs > 0; ofs >>= 1) x = fmaxf(x, __shfl_xor_sync(0xffffffffu, x, ofs));
    if ((tid & 31) == 0) sred[tid >> 5] = x;
    __syncthreads();
    if (tid == 0) {
        float y = sred[0];
#pragma unroll
        for (int w = 1; w < 8; ++w) y = fmaxf(y, sred[w]);
        sred[0] = y;
    }
    __syncthreads();
    const float m1 = sred[0];
    __syncthreads();

    // softmax 1: exp + sum
    float su = 0.0f;
#pragma unroll
    for (int i = 0; i < 8; ++i) {
        v[i] = __expf(v[i] - m1);
        su += v[i];
    }
#pragma unroll
    for (int ofs = 16; ofs > 0; ofs >>= 1) su += __shfl_xor_sync(0xffffffffu, su, ofs);
    if ((tid & 31) == 0) sred[tid >> 5] = su;
    __syncthreads();
    if (tid == 0) {
        float y = 0.0f;
#pragma unroll
        for (int w = 0; w < 8; ++w) y += sred[w];
        sred[0] = y;
    }
    __syncthreads();
    const float inv1 = 1.0f / sred[0];
    __syncthreads();

#pragma unroll
    for (int i = 0; i < 8; ++i) v[i] *= inv1;

    // softmax 2: masked max
    float x2 = -1.0e30f;
#pragma unroll
    for (int i = 0; i < 8; ++i)
        if (m[i]) x2 = fmaxf(x2, v[i]);
#pragma unroll
    for (int ofs = 16; ofs > 0; ofs >>= 1) x2 = fmaxf(x2, __shfl_xor_sync(0xffffffffu, x2, ofs));
    if ((tid & 31) == 0) sred[tid >> 5] = x2;
    __syncthreads();
    if (tid == 0) {
        float y = sred[0];
#pragma unroll
        for (int w = 1; w < 8; ++w) y = fmaxf(y, sred[w]);
        sred[0] = y;
    }
    __syncthreads();
    const float m2 = sred[0];
    __syncthreads();

    if (m2 < -1.0e29f) {
        const __half u = __float2half_rn(1.0f / 2048.0f);
#pragma unroll
        for (int i = 0; i < 8; ++i) o[tid + (i << 8)] = u;
        return;
    }

    // softmax 2: masked exp + sum
    float su2 = 0.0f;
#pragma unroll
    for (int i = 0; i < 8; ++i) {
        const float e = m[i] ? __expf(v[i] - m2) : 0.0f;
        v[i] = e;
        su2 += e;
    }
#pragma unroll
    for (int ofs = 16; ofs > 0; ofs >>= 1) su2 += __shfl_xor_sync(0xffffffffu, su2, ofs);
    if ((tid & 31) == 0) sred[tid >> 5] = su2;
    __syncthreads();
    if (tid == 0) {
        float y = 0.0f;
#pragma unroll
        for (int w = 0; w < 8; ++w) y += sred[w];
        sred[0] = y;
    }
    __syncthreads();
    const float inv2 = 1.0f / sred[0];

#pragma unroll
    for (int i = 0; i < 8; ++i) o[tid + (i << 8)] = __float2half_rn(v[i] * inv2);
}

// ---------------------------------------------------------------------------
// Launch
// ---------------------------------------------------------------------------
extern "C" void kernel_launch(void* const* d_in, const int* in_sizes, int n_in,
                              void* d_out, int out_size)
{
    (void)in_sizes; (void)n_in; (void)out_size;

    const float* x     = (const float*)d_in[0];
    const int*   mask  = (const int*)d_in[1];
    const float* W_qkv = (const float*)d_in[2];
    const float* b_qkv = (const float*)d_in[3];
    const float* W_out = (const float*)d_in[4];
    const float* b_out = (const float*)d_in[5];
    float* out = (float*)d_out;

    __half *xh, *qkv, *wbuf, *att, *vT, *wqkvT, *woutT;
    float *scores;
    cudaGetSymbolAddress((void**)&xh, g_xh);
    cudaGetSymbolAddress((void**)&qkv, g_qkv);
    cudaGetSymbolAddress((void**)&scores, g_scores);
    cudaGetSymbolAddress((void**)&wbuf, g_w);
    cudaGetSymbolAddress((void**)&att, g_att);
    cudaGetSymbolAddress((void**)&vT, g_vT);
    cudaGetSymbolAddress((void**)&wqkvT, g_wqkvT);
    cudaGetSymbolAddress((void**)&woutT, g_woutT);

    cudaFuncSetAttribute(gemm_tc<true,  true >, cudaFuncAttributeMaxDynamicSharedMemorySize, GEMM_SMEM);
    cudaFuncSetAttribute(gemm_tc<false, false>, cudaFuncAttributeMaxDynamicSharedMemorySize, GEMM_SMEM);
    cudaFuncSetAttribute(gemm_tc<false, true >, cudaFuncAttributeMaxDynamicSharedMemorySize, GEMM_SMEM);
    cudaFuncSetAttribute(gemm_tc<true,  false>, cudaFuncAttributeMaxDynamicSharedMemorySize, GEMM_SMEM);

    const int ROWS = BBATCH * SEQ;                     // 16384
    const long long sQKV = (long long)SEQ * 3 * DIM;
    const long long sSC  = (long long)SEQ * SEQ;
    const long long sAT  = (long long)SEQ * DIM;
    const long long sVT  = (long long)DIM * SEQ;

    // 0) x -> fp16
    f2h_copy<<<4096, 256>>>((const float4*)x, (uint2*)xh, ROWS * DIM / 4);

    // 0b) transpose weights -> fp16
    transpose_f2h<<<dim3(3 * DIM / 32, DIM / 32, 1), dim3(32, 8)>>>(
        W_qkv, wqkvT, 3 * DIM, DIM);
    transpose_f2h<<<dim3(DIM / 32, DIM / 32, 1), dim3(32, 8)>>>(
        W_out, woutT, DIM, DIM);

    // 1) qkv = x @ W_qkv + b_qkv   (fp16 out)
    gemm_tc<true, true><<<dim3(3 * DIM / BN, ROWS / BM, 1), 256, GEMM_SMEM>>>(
        xh, wqkvT, qkv, b_qkv, DIM, DIM, 3 * DIM, 0, 0, 0, DIM, 1.0f);

    // 1b) V^T per batch (fp16)
    transpose_h2h<<<dim3(DIM / 32, SEQ / 32, BBATCH), dim3(32, 8)>>>(
        qkv + 2 * DIM, vT, 3 * DIM, SEQ, sQKV, sVT);

    // 2) scores = Q @ K^T / 32   (fp32 out)
    gemm_tc<false, false><<<dim3(SEQ / BN, SEQ / BM, BBATCH), 256, GEMM_SMEM>>>(
        qkv, qkv + DIM, scores, nullptr, 3 * DIM, 3 * DIM, SEQ,
        sQKV, sQKV, sSC, DIM, 0.03125f);

    // 3) dual softmax + mask : fp32 scores -> fp16 w
    dual_softmax_k<<<ROWS, 256>>>(scores, mask, wbuf);

    // 4) att = w @ V   (fp16 out)
    gemm_tc<false, true><<<dim3(DIM / BN, SEQ / BM, BBATCH), 256, GEMM_SMEM>>>(
        wbuf, vT, att, nullptr, SEQ, SEQ, DIM,
        sSC, sVT, sAT, SEQ, 1.0f);

    // 5) out = att @ W_out + b_out  (fp32 out)
    gemm_tc<true, false><<<dim3(DIM / BN, ROWS / BM, 1), 256, GEMM_SMEM>>>(
        att, woutT, out, b_out, DIM, DIM, DIM, 0, 0, 0, DIM, 1.0f);
}

// round 12
// speedup vs baseline: 2.0164x; 1.0156x over previous
#include <cuda_runtime.h>
#include <cuda_fp16.h>
#include <cstdint>
#include <math.h>

// ---------------------------------------------------------------------------
// Problem sizes
// ---------------------------------------------------------------------------
constexpr int BBATCH = 8;
constexpr int SEQ    = 2048;
constexpr int DIM    = 1024;

// ---------------------------------------------------------------------------
// Scratch (static device globals — allocation-guard safe)
// ---------------------------------------------------------------------------
__device__ __half g_xh    [(size_t)BBATCH * SEQ * DIM];      // 32 MB
__device__ __half g_qkv   [(size_t)BBATCH * SEQ * 3 * DIM];  // 96 MB (Q|K|V fp16)
__device__ float  g_scores[(size_t)BBATCH * SEQ * SEQ];      // 128 MB fp32
__device__ __half g_w     [(size_t)BBATCH * SEQ * SEQ];      // 64 MB fp16 weights
__device__ __half g_att   [(size_t)BBATCH * SEQ * DIM];      // 32 MB
__device__ __half g_vT    [(size_t)BBATCH * DIM * SEQ];      // 32 MB
__device__ __half g_wqkvT [(size_t)3 * DIM * DIM];           //  6 MB
__device__ __half g_woutT [(size_t)DIM * DIM];               //  2 MB

// ---------------------------------------------------------------------------
// Helpers (baseline PTX only)
// ---------------------------------------------------------------------------
__device__ __forceinline__ uint32_t h2_as_u32(__half2 h) {
    uint32_t u;
    __builtin_memcpy(&u, &h, 4);
    return u;
}

__device__ __forceinline__ uint32_t s2u(const void* p) {
    uint32_t a;
    asm("{ .reg .u64 t; cvta.to.shared.u64 t, %1; cvt.u32.u64 %0, t; }"
        : "=r"(a) : "l"(p));
    return a;
}

__device__ __forceinline__ void cpa16(uint32_t s, const void* g) {
    asm volatile("cp.async.cg.shared.global [%0], [%1], 16;" :: "r"(s), "l"(g));
}

__device__ __forceinline__ void ldsm4(uint32_t r[4], uint32_t addr) {
    asm volatile("ldmatrix.sync.aligned.m8n8.x4.shared.b16 {%0,%1,%2,%3}, [%4];"
                 : "=r"(r[0]), "=r"(r[1]), "=r"(r[2]), "=r"(r[3]) : "r"(addr));
}

// fp16 MMA, fp32 accumulate: D(16x8) += A(16x16) * B(16x8)
__device__ __forceinline__ void mma16(float c[4], const uint32_t a[4],
                                      uint32_t b0, uint32_t b1) {
    asm volatile(
        "mma.sync.aligned.m16n8k16.row.col.f32.f16.f16.f32 "
        "{%0,%1,%2,%3}, {%4,%5,%6,%7}, {%8,%9}, {%0,%1,%2,%3};"
        : "+f"(c[0]), "+f"(c[1]), "+f"(c[2]), "+f"(c[3])
        : "r"(a[0]), "r"(a[1]), "r"(a[2]), "r"(a[3]), "r"(b0), "r"(b1));
}

// ---------------------------------------------------------------------------
// fp16 mma.sync GEMM:  C[M,N] = alpha * A[M,K] @ B[N,K]^T (+bias)
// A,B fp16 K-major; C fp32 or fp16 (OUTHALF). CTA tile 128x64, BK=64 halves
// (128B rows), 3-stage cp.async, 128 threads, 4 warps of 64x32.
// 3 CTAs/SM (73 KB smem each), reg cap 170 -> ptxas can double-buffer frags.
// ---------------------------------------------------------------------------
constexpr int BM = 128, BN = 64, BK = 64, STAGES = 3;
constexpr int ATILE   = BM * BK * 2;            // 16 KB
constexpr int BTILE   = BN * BK * 2;            //  8 KB
constexpr int STAGE_B = ATILE + BTILE;          // 24 KB
constexpr int GEMM_SMEM = STAGES * STAGE_B + 1024;   // 73.75 KB

template <bool BIAS, bool OUTHALF>
__global__ __launch_bounds__(128, 3)
void gemm_tc(const __half* __restrict__ Ag, const __half* __restrict__ Bg,
             void* __restrict__ Cg, const float* __restrict__ bias,
             int lda, int ldb, int ldc,
             long long sA, long long sB, long long sC,
             int K, float alpha)
{
    extern __shared__ char smem_raw[];
    const uint32_t sb = (s2u(smem_raw) + 1023u) & ~1023u;

    const int tid = threadIdx.x, lane = tid & 31, wid = tid >> 5;
    const int wm = wid & 1;          // 0..1 : 64-row slab
    const int wn = wid >> 1;         // 0..1 : 32-col slab
    const int m0 = blockIdx.y * BM, n0 = blockIdx.x * BN;

    const __half* A = Ag + (size_t)blockIdx.z * sA;
    const __half* B = Bg + (size_t)blockIdx.z * sB;
    const int nk = K / BK;

    // ---- loader: 128 threads; A rows r0+16i (i<8), B rows r0+16i (i<4)
    const int r0 = tid >> 3;                   // 0..15
    const int kq = tid & 7;
    const uint32_t scol = ((uint32_t)(kq * 16)) ^ ((uint32_t)((r0 & 7) << 4));

    const __half* Arow = A + (size_t)(m0 + r0) * lda + kq * 8;
    const __half* Brow = B + (size_t)(n0 + r0) * ldb + kq * 8;

    // ---- ldmatrix mapping ----
    const int  rbase = lane & 15;
    const uint32_t xorv = (uint32_t)((lane & 7) << 4);
    const uint32_t kq16 = (uint32_t)((lane >> 4) << 4);   // 0 or 16 bytes

    float acc[4][4][4];
#pragma unroll
    for (int a = 0; a < 4; a++)
#pragma unroll
        for (int b = 0; b < 4; b++)
#pragma unroll
            for (int c = 0; c < 4; c++) acc[a][b][c] = 0.0f;

#define LOAD_STAGE(s, kc)                                                      \
    do {                                                                       \
        const uint32_t ab = sb + (s) * STAGE_B;                                \
        const __half* ap = Arow + (size_t)(kc) * BK;                           \
        const __half* bp = Brow + (size_t)(kc) * BK;                           \
        _Pragma("unroll")                                                      \
        for (int i = 0; i < 8; i++)                                            \
            cpa16(ab + (uint32_t)((r0 + 16 * i) * 128) + scol,                 \
                  ap + (size_t)(16 * i) * lda);                                \
        _Pragma("unroll")                                                      \
        for (int i = 0; i < 4; i++)                                            \
            cpa16(ab + ATILE + (uint32_t)((r0 + 16 * i) * 128) + scol,         \
                  bp + (size_t)(16 * i) * ldb);                                \
    } while (0)

    LOAD_STAGE(0, 0);
    asm volatile("cp.async.commit_group;");
    LOAD_STAGE(1, 1);
    asm volatile("cp.async.commit_group;");

    for (int kc = 0; kc < nk; kc++) {
        asm volatile("cp.async.wait_group 1;");
        __syncthreads();

        if (kc + 2 < nk) {
            const int s = (kc + 2) % STAGES;
            LOAD_STAGE(s, kc + 2);
        }
        asm volatile("cp.async.commit_group;");

        // ---- compute on stage kc%STAGES: 4 k-steps of k16 ----
        const uint32_t stg = sb + (kc % STAGES) * STAGE_B;
        const uint32_t aB = stg + (uint32_t)((wm * 64 + rbase) * 128);
        const uint32_t bB = stg + ATILE + (uint32_t)((wn * 32 + rbase) * 128);
#pragma unroll
        for (int ks = 0; ks < 4; ks++) {
            const uint32_t kt = ((uint32_t)(ks * 32) + kq16) ^ xorv;
            uint32_t af[4][4], bf[2][4];
#pragma unroll
            for (int mt = 0; mt < 4; mt++) ldsm4(af[mt], aB + mt * 16 * 128 + kt);
#pragma unroll
            for (int bp = 0; bp < 2; bp++) ldsm4(bf[bp], bB + bp * 16 * 128 + kt);
#pragma unroll
            for (int mt = 0; mt < 4; mt++)
#pragma unroll
                for (int bp = 0; bp < 2; bp++) {
                    mma16(acc[mt][2 * bp + 0], af[mt], bf[bp][0], bf[bp][2]);
                    mma16(acc[mt][2 * bp + 1], af[mt], bf[bp][1], bf[bp][3]);
                }
        }
    }
#undef LOAD_STAGE

    // ---- epilogue ----
    const int g = lane >> 2, tg = lane & 3;
#pragma unroll
    for (int mt = 0; mt < 4; mt++) {
        const size_t rw0 = (size_t)(m0 + wm * 64 + mt * 16 + g) * ldc;
        const size_t rw1 = rw0 + (size_t)8 * ldc;
#pragma unroll
        for (int nn = 0; nn < 4; nn++) {
            const int col = n0 + wn * 32 + nn * 8 + tg * 2;
            float2 v0, v1;
            v0.x = acc[mt][nn][0] * alpha;
            v0.y = acc[mt][nn][1] * alpha;
            v1.x = acc[mt][nn][2] * alpha;
            v1.y = acc[mt][nn][3] * alpha;
            if (BIAS) {
                const float b0 = bias[col], b1 = bias[col + 1];
                v0.x += b0; v0.y += b1;
                v1.x += b0; v1.y += b1;
            }
            if (OUTHALF) {
                __half* C = (__half*)Cg + (size_t)blockIdx.z * sC;
                *(__half2*)(C + rw0 + col) = __floats2half2_rn(v0.x, v0.y);
                *(__half2*)(C + rw1 + col) = __floats2half2_rn(v1.x, v1.y);
            } else {
                float* C = (float*)Cg + (size_t)blockIdx.z * sC;
                *(float2*)(C + rw0 + col) = v0;
                *(float2*)(C + rw1 + col) = v1;
            }
        }
    }
}

// ---------------------------------------------------------------------------
// fp32 -> fp16 copy (for x)
// ---------------------------------------------------------------------------
__global__ void f2h_copy(const float4* __restrict__ in, uint2* __restrict__ out, int n4)
{
    for (int i = blockIdx.x * blockDim.x + threadIdx.x; i < n4; i += gridDim.x * blockDim.x) {
        float4 v = in[i];
        uint2 o;
        o.x = h2_as_u32(__floats2half2_rn(v.x, v.y));
        o.y = h2_as_u32(__floats2half2_rn(v.z, v.w));
        out[i] = o;
    }
}

// ---------------------------------------------------------------------------
// Tiled transpose, float src -> half dst  (weights)
// ---------------------------------------------------------------------------
__global__ void transpose_f2h(const float* __restrict__ src, __half* __restrict__ dst,
                              int ldS, int ldD)
{
    __shared__ float t[32][33];
    const int c0 = blockIdx.x * 32, r0 = blockIdx.y * 32;
    const int tx = threadIdx.x, ty = threadIdx.y;
#pragma unroll
    for (int i = 0; i < 32; i += 8)
        t[ty + i][tx] = src[(size_t)(r0 + ty + i) * ldS + c0 + tx];
    __syncthreads();
#pragma unroll
    for (int i = 0; i < 32; i += 8)
        dst[(size_t)(c0 + ty + i) * ldD + r0 + tx] = __float2half_rn(t[tx][ty + i]);
}

// ---------------------------------------------------------------------------
// Tiled transpose, half src -> half dst (V^T), batched
// ---------------------------------------------------------------------------
__global__ void transpose_h2h(const __half* __restrict__ src, __half* __restrict__ dst,
                              int ldS, int ldD, long long sS, long long sD)
{
    __shared__ __half t[32][34];
    src += (size_t)blockIdx.z * sS;
    dst += (size_t)blockIdx.z * sD;
    const int c0 = blockIdx.x * 32, r0 = blockIdx.y * 32;
    const int tx = threadIdx.x, ty = threadIdx.y;
#pragma unroll
    for (int i = 0; i < 32; i += 8)
        t[ty + i][tx] = src[(size_t)(r0 + ty + i) * ldS + c0 + tx];
    __syncthreads();
#pragma unroll
    for (int i = 0; i < 32; i += 8)
        dst[(size_t)(c0 + ty + i) * ldD + r0 + tx] = t[tx][ty + i];
}

// ---------------------------------------------------------------------------
// Fused dual softmax with mask-fill: fp32 scores in, fp16 weights out.
// One CTA per (b,q) row of 2048; 256 threads, 8 values each.
// ---------------------------------------------------------------------------
__global__ __launch_bounds__(256)
void dual_softmax_k(const float* __restrict__ scores, const int* __restrict__ mask,
                    __half* __restrict__ wout)
{
    const long long row = blockIdx.x;
    const float* s = scores + row * 2048;
    const int* mk = mask + row * 2048;
    __half* o = wout + row * 2048;
    const int tid = threadIdx.x;

    float v[8];
    int m[8];
#pragma unroll
    for (int i = 0; i < 8; ++i) {
        v[i] = s[tid + (i << 8)];
        m[i] = mk[tid + (i << 8)];
    }

    __shared__ float sred[8];

    // softmax 1: max
    float x = -3.0e38f;
#pragma unroll
    for (int i = 0; i < 8; ++i) x = fmaxf(x, v[i]);
#pragma unroll
    for (int ofs = 16; ofs > 0; ofs >>= 1) x = fmaxf(x, __shfl_xor_sync(0xffffffffu, x, ofs));
    if ((tid & 31) == 0) sred[tid >> 5] = x;
    __syncthreads();
    if (tid == 0) {
        float y = sred[0];
#pragma unroll
        for (int w = 1; w < 8; ++w) y = fmaxf(y, sred[w]);
        sred[0] = y;
    }
    __syncthreads();
    const float m1 = sred[0];
    __syncthreads();

    // softmax 1: exp + sum
    float su = 0.0f;
#pragma unroll
    for (int i = 0; i < 8; ++i) {
        v[i] = __expf(v[i] - m1);
        su += v[i];
    }
#pragma unroll
    for (int ofs = 16; ofs > 0; ofs >>= 1) su += __shfl_xor_sync(0xffffffffu, su, ofs);
    if ((tid & 31) == 0) sred[tid >> 5] = su;
    __syncthreads();
    if (tid == 0) {
        float y = 0.0f;
#pragma unroll
        for (int w = 0; w < 8; ++w) y += sred[w];
        sred[0] = y;
    }
    __syncthreads();
    const float inv1 = 1.0f / sred[0];
    __syncthreads();

#pragma unroll
    for (int i = 0; i < 8; ++i) v[i] *= inv1;

    // softmax 2: masked max
    float x2 = -1.0e30f;
#pragma unroll
    for (int i = 0; i < 8; ++i)
        if (m[i]) x2 = fmaxf(x2, v[i]);
#pragma unroll
    for (int ofs = 16; ofs > 0; ofs >>= 1) x2 = fmaxf(x2, __shfl_xor_sync(0xffffffffu, x2, ofs));
    if ((tid & 31) == 0) sred[tid >> 5] = x2;
    __syncthreads();
    if (tid == 0) {
        float y = sred[0];
#pragma unroll
        for (int w = 1; w < 8; ++w) y = fmaxf(y, sred[w]);
        sred[0] = y;
    }
    __syncthreads();
    const float m2 = sred[0];
    __syncthreads();

    if (m2 < -1.0e29f) {
        const __half u = __float2half_rn(1.0f / 2048.0f);
#pragma unroll
        for (int i = 0; i < 8; ++i) o[tid + (i << 8)] = u;
        return;
    }

    // softmax 2: masked exp + sum
    float su2 = 0.0f;
#pragma unroll
    for (int i = 0; i < 8; ++i) {
        const float e = m[i] ? __expf(v[i] - m2) : 0.0f;
        v[i] = e;
        su2 += e;
    }
#pragma unroll
    for (int ofs = 16; ofs > 0; ofs >>= 1) su2 += __shfl_xor_sync(0xffffffffu, su2, ofs);
    if ((tid & 31) == 0) sred[tid >> 5] = su2;
    __syncthreads();
    if (tid == 0) {
        float y = 0.0f;
#pragma unroll
        for (int w = 0; w < 8; ++w) y += sred[w];
        sred[0] = y;
    }
    __syncthreads();
    const float inv2 = 1.0f / sred[0];

#pragma unroll
    for (int i = 0; i < 8; ++i) o[tid + (i << 8)] = __float2half_rn(v[i] * inv2);
}

// ---------------------------------------------------------------------------
// Launch
// ---------------------------------------------------------------------------
extern "C" void kernel_launch(void* const* d_in, const int* in_sizes, int n_in,
                              void* d_out, int out_size)
{
    (void)in_sizes; (void)n_in; (void)out_size;

    const float* x     = (const float*)d_in[0];
    const int*   mask  = (const int*)d_in[1];
    const float* W_qkv = (const float*)d_in[2];
    const float* b_qkv = (const float*)d_in[3];
    const float* W_out = (const float*)d_in[4];
    const float* b_out = (const float*)d_in[5];
    float* out = (float*)d_out;

    __half *xh, *qkv, *wbuf, *att, *vT, *wqkvT, *woutT;
    float *scores;
    cudaGetSymbolAddress((void**)&xh, g_xh);
    cudaGetSymbolAddress((void**)&qkv, g_qkv);
    cudaGetSymbolAddress((void**)&scores, g_scores);
    cudaGetSymbolAddress((void**)&wbuf, g_w);
    cudaGetSymbolAddress((void**)&att, g_att);
    cudaGetSymbolAddress((void**)&vT, g_vT);
    cudaGetSymbolAddress((void**)&wqkvT, g_wqkvT);
    cudaGetSymbolAddress((void**)&woutT, g_woutT);

    cudaFuncSetAttribute(gemm_tc<true,  true >, cudaFuncAttributeMaxDynamicSharedMemorySize, GEMM_SMEM);
    cudaFuncSetAttribute(gemm_tc<false, false>, cudaFuncAttributeMaxDynamicSharedMemorySize, GEMM_SMEM);
    cudaFuncSetAttribute(gemm_tc<false, true >, cudaFuncAttributeMaxDynamicSharedMemorySize, GEMM_SMEM);
    cudaFuncSetAttribute(gemm_tc<true,  false>, cudaFuncAttributeMaxDynamicSharedMemorySize, GEMM_SMEM);

    const int ROWS = BBATCH * SEQ;                     // 16384
    const long long sQKV = (long long)SEQ * 3 * DIM;
    const long long sSC  = (long long)SEQ * SEQ;
    const long long sAT  = (long long)SEQ * DIM;
    const long long sVT  = (long long)DIM * SEQ;

    // 0) x -> fp16
    f2h_copy<<<4096, 256>>>((const float4*)x, (uint2*)xh, ROWS * DIM / 4);

    // 0b) transpose weights -> fp16
    transpose_f2h<<<dim3(3 * DIM / 32, DIM / 32, 1), dim3(32, 8)>>>(
        W_qkv, wqkvT, 3 * DIM, DIM);
    transpose_f2h<<<dim3(DIM / 32, DIM / 32, 1), dim3(32, 8)>>>(
        W_out, woutT, DIM, DIM);

    // 1) qkv = x @ W_qkv + b_qkv   (fp16 out)
    gemm_tc<true, true><<<dim3(3 * DIM / BN, ROWS / BM, 1), 128, GEMM_SMEM>>>(
        xh, wqkvT, qkv, b_qkv, DIM, DIM, 3 * DIM, 0, 0, 0, DIM, 1.0f);

    // 1b) V^T per batch (fp16)
    transpose_h2h<<<dim3(DIM / 32, SEQ / 32, BBATCH), dim3(32, 8)>>>(
        qkv + 2 * DIM, vT, 3 * DIM, SEQ, sQKV, sVT);

    // 2) scores = Q @ K^T / 32   (fp32 out)
    gemm_tc<false, false><<<dim3(SEQ / BN, SEQ / BM, BBATCH), 128, GEMM_SMEM>>>(
        qkv, qkv + DIM, scores, nullptr, 3 * DIM, 3 * DIM, SEQ,
        sQKV, sQKV, sSC, DIM, 0.03125f);

    // 3) dual softmax + mask : fp32 scores -> fp16 w
    dual_softmax_k<<<ROWS, 256>>>(scores, mask, wbuf);

    // 4) att = w @ V   (fp16 out)
    gemm_tc<false, true><<<dim3(DIM / BN, SEQ / BM, BBATCH), 128, GEMM_SMEM>>>(
        wbuf, vT, att, nullptr, SEQ, SEQ, DIM,
        sSC, sVT, sAT, SEQ, 1.0f);

    // 5) out = att @ W_out + b_out  (fp32 out)
    gemm_tc<true, false><<<dim3(DIM / BN, ROWS / BM, 1), 128, GEMM_SMEM>>>(
        att, woutT, out, b_out, DIM, DIM, DIM, 0, 0, 0, DIM, 1.0f);
}

// round 13
// speedup vs baseline: 2.0253x; 1.0044x over previous
#include <cuda_runtime.h>
#include <cuda_fp16.h>
#include <cstdint>
#include <math.h>

// ---------------------------------------------------------------------------
// Problem sizes
// ---------------------------------------------------------------------------
constexpr int BBATCH = 8;
constexpr int SEQ    = 2048;
constexpr int DIM    = 1024;

// ---------------------------------------------------------------------------
// Scratch (static device globals — allocation-guard safe)
// ---------------------------------------------------------------------------
__device__ __half g_xh    [(size_t)BBATCH * SEQ * DIM];      // 32 MB
__device__ __half g_qkv   [(size_t)BBATCH * SEQ * 3 * DIM];  // 96 MB (Q|K|V fp16)
__device__ float  g_scores[(size_t)BBATCH * SEQ * SEQ];      // 128 MB fp32
__device__ __half g_w     [(size_t)BBATCH * SEQ * SEQ];      // 64 MB fp16 weights
__device__ __half g_att   [(size_t)BBATCH * SEQ * DIM];      // 32 MB
__device__ __half g_vT    [(size_t)BBATCH * DIM * SEQ];      // 32 MB
__device__ __half g_wqkvT [(size_t)3 * DIM * DIM];           //  6 MB
__device__ __half g_woutT [(size_t)DIM * DIM];               //  2 MB

// ---------------------------------------------------------------------------
// Helpers (baseline PTX only)
// ---------------------------------------------------------------------------
__device__ __forceinline__ uint32_t h2_as_u32(__half2 h) {
    uint32_t u;
    __builtin_memcpy(&u, &h, 4);
    return u;
}

__device__ __forceinline__ uint32_t s2u(const void* p) {
    uint32_t a;
    asm("{ .reg .u64 t; cvta.to.shared.u64 t, %1; cvt.u32.u64 %0, t; }"
        : "=r"(a) : "l"(p));
    return a;
}

__device__ __forceinline__ void cpa16(uint32_t s, const void* g) {
    asm volatile("cp.async.cg.shared.global [%0], [%1], 16;" :: "r"(s), "l"(g));
}

__device__ __forceinline__ void ldsm4(uint32_t r[4], uint32_t addr) {
    asm volatile("ldmatrix.sync.aligned.m8n8.x4.shared.b16 {%0,%1,%2,%3}, [%4];"
                 : "=r"(r[0]), "=r"(r[1]), "=r"(r[2]), "=r"(r[3]) : "r"(addr));
}

// fp16 MMA, fp32 accumulate: D(16x8) += A(16x16) * B(16x8)
__device__ __forceinline__ void mma16(float c[4], const uint32_t a[4],
                                      uint32_t b0, uint32_t b1) {
    asm volatile(
        "mma.sync.aligned.m16n8k16.row.col.f32.f16.f16.f32 "
        "{%0,%1,%2,%3}, {%4,%5,%6,%7}, {%8,%9}, {%0,%1,%2,%3};"
        : "+f"(c[0]), "+f"(c[1]), "+f"(c[2]), "+f"(c[3])
        : "r"(a[0]), "r"(a[1]), "r"(a[2]), "r"(a[3]), "r"(b0), "r"(b1));
}

// ---------------------------------------------------------------------------
// fp16 mma.sync GEMM:  C[M,N] = alpha * A[M,K] @ B[N,K]^T (+bias)
// A,B fp16 K-major; C fp32 or fp16 (OUTHALF). CTA tile 128x64, BK=64 halves,
// 3-stage cp.async, 128 threads, 4 warps of 64x32, 3 CTAs/SM.
// Inner loop EXPLICITLY double-buffers ldmatrix fragments across ks steps so
// the tensor pipe never waits on exposed LDSM latency (except first ks/kc).
// ---------------------------------------------------------------------------
constexpr int BM = 128, BN = 64, BK = 64, STAGES = 3;
constexpr int ATILE   = BM * BK * 2;            // 16 KB
constexpr int BTILE   = BN * BK * 2;            //  8 KB
constexpr int STAGE_B = ATILE + BTILE;          // 24 KB
constexpr int GEMM_SMEM = STAGES * STAGE_B + 1024;   // 73.75 KB

template <bool BIAS, bool OUTHALF>
__global__ __launch_bounds__(128, 3)
void gemm_tc(const __half* __restrict__ Ag, const __half* __restrict__ Bg,
             void* __restrict__ Cg, const float* __restrict__ bias,
             int lda, int ldb, int ldc,
             long long sA, long long sB, long long sC,
             int K, float alpha)
{
    extern __shared__ char smem_raw[];
    const uint32_t sb = (s2u(smem_raw) + 1023u) & ~1023u;

    const int tid = threadIdx.x, lane = tid & 31, wid = tid >> 5;
    const int wm = wid & 1;          // 0..1 : 64-row slab
    const int wn = wid >> 1;         // 0..1 : 32-col slab
    const int m0 = blockIdx.y * BM, n0 = blockIdx.x * BN;

    const __half* A = Ag + (size_t)blockIdx.z * sA;
    const __half* B = Bg + (size_t)blockIdx.z * sB;
    const int nk = K / BK;

    // ---- loader: 128 threads; A rows r0+16i (i<8), B rows r0+16i (i<4)
    const int r0 = tid >> 3;                   // 0..15
    const int kq = tid & 7;
    const uint32_t scol = ((uint32_t)(kq * 16)) ^ ((uint32_t)((r0 & 7) << 4));

    const __half* Arow = A + (size_t)(m0 + r0) * lda + kq * 8;
    const __half* Brow = B + (size_t)(n0 + r0) * ldb + kq * 8;

    // ---- ldmatrix mapping ----
    const int  rbase = lane & 15;
    const uint32_t xorv = (uint32_t)((lane & 7) << 4);
    const uint32_t kq16 = (uint32_t)((lane >> 4) << 4);   // 0 or 16 bytes

    float acc[4][4][4];
#pragma unroll
    for (int a = 0; a < 4; a++)
#pragma unroll
        for (int b = 0; b < 4; b++)
#pragma unroll
            for (int c = 0; c < 4; c++) acc[a][b][c] = 0.0f;

#define LOAD_STAGE(s, kc)                                                      \
    do {                                                                       \
        const uint32_t ab = sb + (s) * STAGE_B;                                \
        const __half* ap = Arow + (size_t)(kc) * BK;                           \
        const __half* bp = Brow + (size_t)(kc) * BK;                           \
        _Pragma("unroll")                                                      \
        for (int i = 0; i < 8; i++)                                            \
            cpa16(ab + (uint32_t)((r0 + 16 * i) * 128) + scol,                 \
                  ap + (size_t)(16 * i) * lda);                                \
        _Pragma("unroll")                                                      \
        for (int i = 0; i < 4; i++)                                            \
            cpa16(ab + ATILE + (uint32_t)((r0 + 16 * i) * 128) + scol,         \
                  bp + (size_t)(16 * i) * ldb);                                \
    } while (0)

    LOAD_STAGE(0, 0);
    asm volatile("cp.async.commit_group;");
    LOAD_STAGE(1, 1);
    asm volatile("cp.async.commit_group;");

    for (int kc = 0; kc < nk; kc++) {
        asm volatile("cp.async.wait_group 1;");
        __syncthreads();

        if (kc + 2 < nk) {
            const int s = (kc + 2) % STAGES;
            LOAD_STAGE(s, kc + 2);
        }
        asm volatile("cp.async.commit_group;");

        // ---- compute on stage kc%STAGES: 4 k-steps of k16, fragments
        //      double-buffered so ks+1 LDSM overlaps ks MMAs ----
        const uint32_t stg = sb + (kc % STAGES) * STAGE_B;
        const uint32_t aB = stg + (uint32_t)((wm * 64 + rbase) * 128);
        const uint32_t bB = stg + ATILE + (uint32_t)((wn * 32 + rbase) * 128);

        uint32_t af[2][4][4], bf[2][2][4];
        {
            const uint32_t kt0 = kq16 ^ xorv;
#pragma unroll
            for (int mt = 0; mt < 4; mt++) ldsm4(af[0][mt], aB + mt * 16 * 128 + kt0);
#pragma unroll
            for (int bp = 0; bp < 2; bp++) ldsm4(bf[0][bp], bB + bp * 16 * 128 + kt0);
        }
#pragma unroll
        for (int ks = 0; ks < 4; ks++) {
            const int cur = ks & 1, nxt = cur ^ 1;
            if (ks < 3) {
                const uint32_t kt = ((uint32_t)((ks + 1) * 32) + kq16) ^ xorv;
#pragma unroll
                for (int mt = 0; mt < 4; mt++) ldsm4(af[nxt][mt], aB + mt * 16 * 128 + kt);
#pragma unroll
                for (int bp = 0; bp < 2; bp++) ldsm4(bf[nxt][bp], bB + bp * 16 * 128 + kt);
            }
#pragma unroll
            for (int mt = 0; mt < 4; mt++)
#pragma unroll
                for (int bp = 0; bp < 2; bp++) {
                    mma16(acc[mt][2 * bp + 0], af[cur][mt], bf[cur][bp][0], bf[cur][bp][2]);
                    mma16(acc[mt][2 * bp + 1], af[cur][mt], bf[cur][bp][1], bf[cur][bp][3]);
                }
        }
    }
#undef LOAD_STAGE

    // ---- epilogue ----
    const int g = lane >> 2, tg = lane & 3;
#pragma unroll
    for (int mt = 0; mt < 4; mt++) {
        const size_t rw0 = (size_t)(m0 + wm * 64 + mt * 16 + g) * ldc;
        const size_t rw1 = rw0 + (size_t)8 * ldc;
#pragma unroll
        for (int nn = 0; nn < 4; nn++) {
            const int col = n0 + wn * 32 + nn * 8 + tg * 2;
            float2 v0, v1;
            v0.x = acc[mt][nn][0] * alpha;
            v0.y = acc[mt][nn][1] * alpha;
            v1.x = acc[mt][nn][2] * alpha;
            v1.y = acc[mt][nn][3] * alpha;
            if (BIAS) {
                const float b0 = bias[col], b1 = bias[col + 1];
                v0.x += b0; v0.y += b1;
                v1.x += b0; v1.y += b1;
            }
            if (OUTHALF) {
                __half* C = (__half*)Cg + (size_t)blockIdx.z * sC;
                *(__half2*)(C + rw0 + col) = __floats2half2_rn(v0.x, v0.y);
                *(__half2*)(C + rw1 + col) = __floats2half2_rn(v1.x, v1.y);
            } else {
                float* C = (float*)Cg + (size_t)blockIdx.z * sC;
                *(float2*)(C + rw0 + col) = v0;
                *(float2*)(C + rw1 + col) = v1;
            }
        }
    }
}

// ---------------------------------------------------------------------------
// fp32 -> fp16 copy (for x)
// ---------------------------------------------------------------------------
__global__ void f2h_copy(const float4* __restrict__ in, uint2* __restrict__ out, int n4)
{
    for (int i = blockIdx.x * blockDim.x + threadIdx.x; i < n4; i += gridDim.x * blockDim.x) {
        float4 v = in[i];
        uint2 o;
        o.x = h2_as_u32(__floats2half2_rn(v.x, v.y));
        o.y = h2_as_u32(__floats2half2_rn(v.z, v.w));
        out[i] = o;
    }
}

// ---------------------------------------------------------------------------
// Tiled transpose, float src -> half dst  (weights)
// ---------------------------------------------------------------------------
__global__ void transpose_f2h(const float* __restrict__ src, __half* __restrict__ dst,
                              int ldS, int ldD)
{
    __shared__ float t[32][33];
    const int c0 = blockIdx.x * 32, r0 = blockIdx.y * 32;
    const int tx = threadIdx.x, ty = threadIdx.y;
#pragma unroll
    for (int i = 0; i < 32; i += 8)
        t[ty + i][tx] = src[(size_t)(r0 + ty + i) * ldS + c0 + tx];
    __syncthreads();
#pragma unroll
    for (int i = 0; i < 32; i += 8)
        dst[(size_t)(c0 + ty + i) * ldD + r0 + tx] = __float2half_rn(t[tx][ty + i]);
}

// ---------------------------------------------------------------------------
// Tiled transpose, half src -> half dst (V^T), batched
// ---------------------------------------------------------------------------
__global__ void transpose_h2h(const __half* __restrict__ src, __half* __restrict__ dst,
                              int ldS, int ldD, long long sS, long long sD)
{
    __shared__ __half t[32][34];
    src += (size_t)blockIdx.z * sS;
    dst += (size_t)blockIdx.z * sD;
    const int c0 = blockIdx.x * 32, r0 = blockIdx.y * 32;
    const int tx = threadIdx.x, ty = threadIdx.y;
#pragma unroll
    for (int i = 0; i < 32; i += 8)
        t[ty + i][tx] = src[(size_t)(r0 + ty + i) * ldS + c0 + tx];
    __syncthreads();
#pragma unroll
    for (int i = 0; i < 32; i += 8)
        dst[(size_t)(c0 + ty + i) * ldD + r0 + tx] = t[tx][ty + i];
}

// ---------------------------------------------------------------------------
// Fused dual softmax with mask-fill: fp32 scores in, fp16 weights out.
// One CTA per (b,q) row of 2048; 256 threads, 8 values each.
// ---------------------------------------------------------------------------
__global__ __launch_bounds__(256)
void dual_softmax_k(const float* __restrict__ scores, const int* __restrict__ mask,
                    __half* __restrict__ wout)
{
    const long long row = blockIdx.x;
    const float* s = scores + row * 2048;
    const int* mk = mask + row * 2048;
    __half* o = wout + row * 2048;
    const int tid = threadIdx.x;

    float v[8];
    int m[8];
#pragma unroll
    for (int i = 0; i < 8; ++i) {
        v[i] = s[tid + (i << 8)];
        m[i] = mk[tid + (i << 8)];
    }

    __shared__ float sred[8];

    // softmax 1: max
    float x = -3.0e38f;
#pragma unroll
    for (int i = 0; i < 8; ++i) x = fmaxf(x, v[i]);
#pragma unroll
    for (int ofs = 16; ofs > 0; ofs >>= 1) x = fmaxf(x, __shfl_xor_sync(0xffffffffu, x, ofs));
    if ((tid & 31) == 0) sred[tid >> 5] = x;
    __syncthreads();
    if (tid == 0) {
        float y = sred[0];
#pragma unroll
        for (int w = 1; w < 8; ++w) y = fmaxf(y, sred[w]);
        sred[0] = y;
    }
    __syncthreads();
    const float m1 = sred[0];
    __syncthreads();

    // softmax 1: exp + sum
    float su = 0.0f;
#pragma unroll
    for (int i = 0; i < 8; ++i) {
        v[i] = __expf(v[i] - m1);
        su += v[i];
    }
#pragma unroll
    for (int ofs = 16; ofs > 0; ofs >>= 1) su += __shfl_xor_sync(0xffffffffu, su, ofs);
    if ((tid & 31) == 0) sred[tid >> 5] = su;
    __syncthreads();
    if (tid == 0) {
        float y = 0.0f;
#pragma unroll
        for (int w = 0; w < 8; ++w) y += sred[w];
        sred[0] = y;
    }
    __syncthreads();
    const float inv1 = 1.0f / sred[0];
    __syncthreads();

#pragma unroll
    for (int i = 0; i < 8; ++i) v[i] *= inv1;

    // softmax 2: masked max
    float x2 = -1.0e30f;
#pragma unroll
    for (int i = 0; i < 8; ++i)
        if (m[i]) x2 = fmaxf(x2, v[i]);
#pragma unroll
    for (int ofs = 16; ofs > 0; ofs >>= 1) x2 = fmaxf(x2, __shfl_xor_sync(0xffffffffu, x2, ofs));
    if ((tid & 31) == 0) sred[tid >> 5] = x2;
    __syncthreads();
    if (tid == 0) {
        float y = sred[0];
#pragma unroll
        for (int w = 1; w < 8; ++w) y = fmaxf(y, sred[w]);
        sred[0] = y;
    }
    __syncthreads();
    const float m2 = sred[0];
    __syncthreads();

    if (m2 < -1.0e29f) {
        const __half u = __float2half_rn(1.0f / 2048.0f);
#pragma unroll
        for (int i = 0; i < 8; ++i) o[tid + (i << 8)] = u;
        return;
    }

    // softmax 2: masked exp + sum
    float su2 = 0.0f;
#pragma unroll
    for (int i = 0; i < 8; ++i) {
        const float e = m[i] ? __expf(v[i] - m2) : 0.0f;
        v[i] = e;
        su2 += e;
    }
#pragma unroll
    for (int ofs = 16; ofs > 0; ofs >>= 1) su2 += __shfl_xor_sync(0xffffffffu, su2, ofs);
    if ((tid & 31) == 0) sred[tid >> 5] = su2;
    __syncthreads();
    if (tid == 0) {
        float y = 0.0f;
#pragma unroll
        for (int w = 0; w < 8; ++w) y += sred[w];
        sred[0] = y;
    }
    __syncthreads();
    const float inv2 = 1.0f / sred[0];

#pragma unroll
    for (int i = 0; i < 8; ++i) o[tid + (i << 8)] = __float2half_rn(v[i] * inv2);
}

// ---------------------------------------------------------------------------
// Launch
// ---------------------------------------------------------------------------
extern "C" void kernel_launch(void* const* d_in, const int* in_sizes, int n_in,
                              void* d_out, int out_size)
{
    (void)in_sizes; (void)n_in; (void)out_size;

    const float* x     = (const float*)d_in[0];
    const int*   mask  = (const int*)d_in[1];
    const float* W_qkv = (const float*)d_in[2];
    const float* b_qkv = (const float*)d_in[3];
    const float* W_out = (const float*)d_in[4];
    const float* b_out = (const float*)d_in[5];
    float* out = (float*)d_out;

    __half *xh, *qkv, *wbuf, *att, *vT, *wqkvT, *woutT;
    float *scores;
    cudaGetSymbolAddress((void**)&xh, g_xh);
    cudaGetSymbolAddress((void**)&qkv, g_qkv);
    cudaGetSymbolAddress((void**)&scores, g_scores);
    cudaGetSymbolAddress((void**)&wbuf, g_w);
    cudaGetSymbolAddress((void**)&att, g_att);
    cudaGetSymbolAddress((void**)&vT, g_vT);
    cudaGetSymbolAddress((void**)&wqkvT, g_wqkvT);
    cudaGetSymbolAddress((void**)&woutT, g_woutT);

    cudaFuncSetAttribute(gemm_tc<true,  true >, cudaFuncAttributeMaxDynamicSharedMemorySize, GEMM_SMEM);
    cudaFuncSetAttribute(gemm_tc<false, false>, cudaFuncAttributeMaxDynamicSharedMemorySize, GEMM_SMEM);
    cudaFuncSetAttribute(gemm_tc<false, true >, cudaFuncAttributeMaxDynamicSharedMemorySize, GEMM_SMEM);
    cudaFuncSetAttribute(gemm_tc<true,  false>, cudaFuncAttributeMaxDynamicSharedMemorySize, GEMM_SMEM);

    const int ROWS = BBATCH * SEQ;                     // 16384
    const long long sQKV = (long long)SEQ * 3 * DIM;
    const long long sSC  = (long long)SEQ * SEQ;
    const long long sAT  = (long long)SEQ * DIM;
    const long long sVT  = (long long)DIM * SEQ;

    // 0) x -> fp16
    f2h_copy<<<4096, 256>>>((const float4*)x, (uint2*)xh, ROWS * DIM / 4);

    // 0b) transpose weights -> fp16
    transpose_f2h<<<dim3(3 * DIM / 32, DIM / 32, 1), dim3(32, 8)>>>(
        W_qkv, wqkvT, 3 * DIM, DIM);
    transpose_f2h<<<dim3(DIM / 32, DIM / 32, 1), dim3(32, 8)>>>(
        W_out, woutT, DIM, DIM);

    // 1) qkv = x @ W_qkv + b_qkv   (fp16 out)
    gemm_tc<true, true><<<dim3(3 * DIM / BN, ROWS / BM, 1), 128, GEMM_SMEM>>>(
        xh, wqkvT, qkv, b_qkv, DIM, DIM, 3 * DIM, 0, 0, 0, DIM, 1.0f);

    // 1b) V^T per batch (fp16)
    transpose_h2h<<<dim3(DIM / 32, SEQ / 32, BBATCH), dim3(32, 8)>>>(
        qkv + 2 * DIM, vT, 3 * DIM, SEQ, sQKV, sVT);

    // 2) scores = Q @ K^T / 32   (fp32 out)
    gemm_tc<false, false><<<dim3(SEQ / BN, SEQ / BM, BBATCH), 128, GEMM_SMEM>>>(
        qkv, qkv + DIM, scores, nullptr, 3 * DIM, 3 * DIM, SEQ,
        sQKV, sQKV, sSC, DIM, 0.03125f);

    // 3) dual softmax + mask : fp32 scores -> fp16 w
    dual_softmax_k<<<ROWS, 256>>>(scores, mask, wbuf);

    // 4) att = w @ V   (fp16 out)
    gemm_tc<false, true><<<dim3(DIM / BN, SEQ / BM, BBATCH), 128, GEMM_SMEM>>>(
        wbuf, vT, att, nullptr, SEQ, SEQ, DIM,
        sSC, sVT, sAT, SEQ, 1.0f);

    // 5) out = att @ W_out + b_out  (fp32 out)
    gemm_tc<true, false><<<dim3(DIM / BN, ROWS / BM, 1), 128, GEMM_SMEM>>>(
        att, woutT, out, b_out, DIM, DIM, DIM, 0, 0, 0, DIM, 1.0f);
}